// round 1
// baseline (speedup 1.0000x reference)
#include <cuda_runtime.h>
#include <math.h>

#define T_TOK 4096
#define H_DIM 2048
#define I_DIM 1024
#define N_EXP 8

// ---------------- scratch (static device globals; no allocation) ------------
__device__ int   g_count[N_EXP];
__device__ int   g_tok [N_EXP * T_TOK];
__device__ float g_wt  [N_EXP * T_TOK];
__device__ int   g_slot[N_EXP * T_TOK];
__device__ float g_act [(size_t)N_EXP * T_TOK * I_DIM];   // 128 MB
__device__ float g_part[(size_t)T_TOK * 2 * H_DIM];       // 64 MB

// ---------------- init ------------------------------------------------------
__global__ void k_init() {
    if (threadIdx.x < N_EXP) g_count[threadIdx.x] = 0;
}

// ---------------- router: logits -> softmax -> top2 -> scatter --------------
__global__ void k_router(const float* __restrict__ x,
                         const float* __restrict__ gw) {
    int gid  = blockIdx.x * blockDim.x + threadIdx.x;
    int t    = gid >> 5;
    int lane = gid & 31;
    if (t >= T_TOK) return;

    const float* xr = x + (size_t)t * H_DIM;
    float acc[N_EXP];
#pragma unroll
    for (int e = 0; e < N_EXP; e++) acc[e] = 0.f;

    for (int h = lane; h < H_DIM; h += 32) {
        float xv = xr[h];
#pragma unroll
        for (int e = 0; e < N_EXP; e++) acc[e] += xv * gw[e * H_DIM + h];
    }
#pragma unroll
    for (int e = 0; e < N_EXP; e++) {
#pragma unroll
        for (int o = 16; o > 0; o >>= 1)
            acc[e] += __shfl_xor_sync(0xffffffffu, acc[e], o);
    }

    if (lane == 0) {
        float m = acc[0];
#pragma unroll
        for (int e = 1; e < N_EXP; e++) m = fmaxf(m, acc[e]);
        float p[N_EXP];
        float s = 0.f;
#pragma unroll
        for (int e = 0; e < N_EXP; e++) { p[e] = expf(acc[e] - m); s += p[e]; }
        float inv = 1.f / s;
#pragma unroll
        for (int e = 0; e < N_EXP; e++) p[e] *= inv;

        // top-2, lowest index wins ties (matches lax.top_k)
        int e0 = 0;
#pragma unroll
        for (int e = 1; e < N_EXP; e++) if (p[e] > p[e0]) e0 = e;
        int e1 = -1;
#pragma unroll
        for (int e = 0; e < N_EXP; e++) {
            if (e == e0) continue;
            if (e1 < 0 || p[e] > p[e1]) e1 = e;
        }
        float den = p[e0] + p[e1];
        float w0 = p[e0] / den;
        float w1 = p[e1] / den;

        int pos0 = atomicAdd(&g_count[e0], 1);
        g_tok [e0 * T_TOK + pos0] = t;
        g_wt  [e0 * T_TOK + pos0] = w0;
        g_slot[e0 * T_TOK + pos0] = 0;

        int pos1 = atomicAdd(&g_count[e1], 1);
        g_tok [e1 * T_TOK + pos1] = t;
        g_wt  [e1 * T_TOK + pos1] = w1;
        g_slot[e1 * T_TOK + pos1] = 1;
    }
}

// ---------------- GEMM1: act = silu(h @ Wg^T) * (h @ Wu^T) ------------------
// tiles: 64 tokens x 64 inter x 16 K, 256 threads, 4x4 per thread (dual out)
__global__ __launch_bounds__(256) void k_gemm1(const float* __restrict__ x,
                                               const float* __restrict__ wg,
                                               const float* __restrict__ wu) {
    const int e    = blockIdx.z;
    const int n    = g_count[e];
    const int row0 = blockIdx.x * 64;
    if (row0 >= n) return;
    const int col0 = blockIdx.y * 64;

    __shared__ float As[16][64];
    __shared__ float Bg[16][64];
    __shared__ float Bu[16][64];
    __shared__ int   toks[64];

    const int tid = threadIdx.x;
    if (tid < 64) {
        int r = row0 + tid;
        toks[tid] = (r < n) ? g_tok[e * T_TOK + r] : 0;
    }
    __syncthreads();

    const int lr = tid >> 2;   // 0..63 row in tile
    const int lq = tid & 3;    // 0..3  float4 chunk within 16-wide K slab
    const int ta = toks[lr];
    const float* aptr = x  + (size_t)ta * H_DIM + lq * 4;
    const float* gptr = wg + ((size_t)e * I_DIM + col0 + lr) * H_DIM + lq * 4;
    const float* uptr = wu + ((size_t)e * I_DIM + col0 + lr) * H_DIM + lq * 4;

    const int tr = tid >> 4;   // 0..15 token group
    const int tc = tid & 15;   // 0..15 inter group

    float cg[4][4] = {}, cu[4][4] = {};

    for (int k0 = 0; k0 < H_DIM; k0 += 16) {
        float4 av = *(const float4*)(aptr + k0);
        float4 gv = *(const float4*)(gptr + k0);
        float4 uv = *(const float4*)(uptr + k0);
        __syncthreads();
        As[lq * 4 + 0][lr] = av.x; As[lq * 4 + 1][lr] = av.y;
        As[lq * 4 + 2][lr] = av.z; As[lq * 4 + 3][lr] = av.w;
        Bg[lq * 4 + 0][lr] = gv.x; Bg[lq * 4 + 1][lr] = gv.y;
        Bg[lq * 4 + 2][lr] = gv.z; Bg[lq * 4 + 3][lr] = gv.w;
        Bu[lq * 4 + 0][lr] = uv.x; Bu[lq * 4 + 1][lr] = uv.y;
        Bu[lq * 4 + 2][lr] = uv.z; Bu[lq * 4 + 3][lr] = uv.w;
        __syncthreads();
#pragma unroll
        for (int kk = 0; kk < 16; kk++) {
            float4 a = *(const float4*)&As[kk][tr * 4];
            float4 b = *(const float4*)&Bg[kk][tc * 4];
            float4 c = *(const float4*)&Bu[kk][tc * 4];
            float ar[4] = {a.x, a.y, a.z, a.w};
            float br[4] = {b.x, b.y, b.z, b.w};
            float cr[4] = {c.x, c.y, c.z, c.w};
#pragma unroll
            for (int i = 0; i < 4; i++)
#pragma unroll
                for (int j = 0; j < 4; j++) {
                    cg[i][j] += ar[i] * br[j];
                    cu[i][j] += ar[i] * cr[j];
                }
        }
    }

#pragma unroll
    for (int i = 0; i < 4; i++) {
        int rr = row0 + tr * 4 + i;
        if (rr < n) {
            float* dst = &g_act[((size_t)e * T_TOK + rr) * I_DIM + col0 + tc * 4];
#pragma unroll
            for (int j = 0; j < 4; j++) {
                float g = cg[i][j];
                float a = g / (1.f + expf(-g)) * cu[i][j];
                dst[j] = a;
            }
        }
    }
}

// ---------------- GEMM2: part = rw * (act @ Wd^T) ---------------------------
// tiles: 64 tokens x 64 hidden x 16 K (K = I_DIM = 1024)
__global__ __launch_bounds__(256) void k_gemm2(const float* __restrict__ wd) {
    const int e    = blockIdx.z;
    const int n    = g_count[e];
    const int row0 = blockIdx.x * 64;
    if (row0 >= n) return;
    const int col0 = blockIdx.y * 64;

    __shared__ float As[16][64];
    __shared__ float Bd[16][64];
    __shared__ int   toks[64];
    __shared__ float ws[64];
    __shared__ int   ks[64];

    const int tid = threadIdx.x;
    if (tid < 64) {
        int r = row0 + tid;
        if (r < n) {
            toks[tid] = g_tok [e * T_TOK + r];
            ws[tid]   = g_wt  [e * T_TOK + r];
            ks[tid]   = g_slot[e * T_TOK + r];
        } else {
            toks[tid] = 0; ws[tid] = 0.f; ks[tid] = 0;
        }
    }
    __syncthreads();

    const int lr = tid >> 2;
    const int lq = tid & 3;
    int arow = (row0 + lr < n) ? (row0 + lr) : 0;
    const float* aptr = g_act + ((size_t)e * T_TOK + arow) * I_DIM + lq * 4;
    const float* dptr = wd + ((size_t)e * H_DIM + col0 + lr) * I_DIM + lq * 4;

    const int tr = tid >> 4;
    const int tc = tid & 15;

    float cc[4][4] = {};

    for (int k0 = 0; k0 < I_DIM; k0 += 16) {
        float4 av = *(const float4*)(aptr + k0);
        float4 dv = *(const float4*)(dptr + k0);
        __syncthreads();
        As[lq * 4 + 0][lr] = av.x; As[lq * 4 + 1][lr] = av.y;
        As[lq * 4 + 2][lr] = av.z; As[lq * 4 + 3][lr] = av.w;
        Bd[lq * 4 + 0][lr] = dv.x; Bd[lq * 4 + 1][lr] = dv.y;
        Bd[lq * 4 + 2][lr] = dv.z; Bd[lq * 4 + 3][lr] = dv.w;
        __syncthreads();
#pragma unroll
        for (int kk = 0; kk < 16; kk++) {
            float4 a = *(const float4*)&As[kk][tr * 4];
            float4 b = *(const float4*)&Bd[kk][tc * 4];
            float ar[4] = {a.x, a.y, a.z, a.w};
            float br[4] = {b.x, b.y, b.z, b.w};
#pragma unroll
            for (int i = 0; i < 4; i++)
#pragma unroll
                for (int j = 0; j < 4; j++)
                    cc[i][j] += ar[i] * br[j];
        }
    }

#pragma unroll
    for (int i = 0; i < 4; i++) {
        int rloc = tr * 4 + i;
        int rr = row0 + rloc;
        if (rr < n) {
            int   t = toks[rloc];
            float w = ws[rloc];
            int   k = ks[rloc];
            float* dst = &g_part[((size_t)t * 2 + k) * H_DIM + col0 + tc * 4];
#pragma unroll
            for (int j = 0; j < 4; j++)
                dst[j] = w * cc[i][j];
        }
    }
}

// ---------------- combine ----------------------------------------------------
__global__ void k_combine(float* __restrict__ out) {
    int i = blockIdx.x * 256 + threadIdx.x;
    if (i >= T_TOK * H_DIM) return;
    int t = i >> 11;          // / H_DIM
    int h = i & (H_DIM - 1);
    out[i] = g_part[((size_t)t * 2 + 0) * H_DIM + h] +
             g_part[((size_t)t * 2 + 1) * H_DIM + h];
}

// ---------------- launch -----------------------------------------------------
extern "C" void kernel_launch(void* const* d_in, const int* in_sizes, int n_in,
                              void* d_out, int out_size) {
    const float* x  = (const float*)d_in[0];
    const float* gw = (const float*)d_in[1];
    const float* wg = (const float*)d_in[2];
    const float* wu = (const float*)d_in[3];
    const float* wd = (const float*)d_in[4];
    float* out = (float*)d_out;

    k_init<<<1, 32>>>();
    k_router<<<(T_TOK * 32) / 256, 256>>>(x, gw);
    k_gemm1<<<dim3(T_TOK / 64, I_DIM / 64, N_EXP), 256>>>(x, wg, wu);
    k_gemm2<<<dim3(T_TOK / 64, H_DIM / 64, N_EXP), 256>>>(wd);
    k_combine<<<(T_TOK * H_DIM + 255) / 256, 256>>>(out);
}

// round 3
// speedup vs baseline: 2.7371x; 2.7371x over previous
#include <cuda_runtime.h>
#include <cuda_bf16.h>
#include <math.h>
#include <stdint.h>

#define T_TOK 4096
#define H_DIM 2048
#define I_DIM 1024
#define N_EXP 8

// ---------------- scratch (static device globals; no allocation) ------------
__device__ int   g_count[N_EXP];
__device__ int   g_tok [N_EXP * T_TOK];
__device__ float g_wt  [N_EXP * T_TOK];
__device__ int   g_slot[N_EXP * T_TOK];
__device__ float g_part[(size_t)T_TOK * 2 * H_DIM];

// converted bf16 hi/lo operands
__device__ __nv_bfloat16 cx_hi [(size_t)T_TOK * H_DIM];
__device__ __nv_bfloat16 cx_lo [(size_t)T_TOK * H_DIM];
__device__ __nv_bfloat16 cwg_hi[(size_t)N_EXP * I_DIM * H_DIM];
__device__ __nv_bfloat16 cwg_lo[(size_t)N_EXP * I_DIM * H_DIM];
__device__ __nv_bfloat16 cwu_hi[(size_t)N_EXP * I_DIM * H_DIM];
__device__ __nv_bfloat16 cwu_lo[(size_t)N_EXP * I_DIM * H_DIM];
__device__ __nv_bfloat16 cwd_hi[(size_t)N_EXP * H_DIM * I_DIM];
__device__ __nv_bfloat16 cwd_lo[(size_t)N_EXP * H_DIM * I_DIM];
__device__ __nv_bfloat16 act_hi[(size_t)N_EXP * T_TOK * I_DIM];
__device__ __nv_bfloat16 act_lo[(size_t)N_EXP * T_TOK * I_DIM];

// ======================= helpers ============================================
__device__ __forceinline__ uint32_t smem_u32(const void* p) {
    uint32_t a;
    asm("{ .reg .u64 t; cvta.to.shared.u64 t, %1; cvt.u32.u64 %0, t; }"
        : "=r"(a) : "l"(p));
    return a;
}

__device__ __forceinline__ void cp16(uint32_t s, const void* g) {
    asm volatile("cp.async.cg.shared.global [%0], [%1], 16;"
                 :: "r"(s), "l"(g) : "memory");
}
#define CP_COMMIT() asm volatile("cp.async.commit_group;" ::: "memory")
#define CP_WAIT(n)  asm volatile("cp.async.wait_group %0;" :: "n"(n) : "memory")

__device__ __forceinline__ void ldm4(uint32_t& r0, uint32_t& r1,
                                     uint32_t& r2, uint32_t& r3, uint32_t a) {
    asm volatile("ldmatrix.sync.aligned.m8n8.x4.shared.b16 {%0,%1,%2,%3}, [%4];"
                 : "=r"(r0), "=r"(r1), "=r"(r2), "=r"(r3) : "r"(a));
}

__device__ __forceinline__ void mma16816(float* c, uint32_t a0, uint32_t a1,
                                         uint32_t a2, uint32_t a3,
                                         uint32_t b0, uint32_t b1) {
    asm volatile(
        "mma.sync.aligned.m16n8k16.row.col.f32.bf16.bf16.f32 "
        "{%0,%1,%2,%3}, {%4,%5,%6,%7}, {%8,%9}, {%0,%1,%2,%3};"
        : "+f"(c[0]), "+f"(c[1]), "+f"(c[2]), "+f"(c[3])
        : "r"(a0), "r"(a1), "r"(a2), "r"(a3), "r"(b0), "r"(b1));
}

// split two fp32 into bf16 hi pair + lo pair (packed bf16x2)
__device__ __forceinline__ void split2(float a, float b, uint32_t& h, uint32_t& l) {
    __nv_bfloat162 hv = __floats2bfloat162_rn(a, b);
    float2 hf = __bfloat1622float2(hv);
    __nv_bfloat162 lv = __floats2bfloat162_rn(a - hf.x, b - hf.y);
    h = *reinterpret_cast<uint32_t*>(&hv);
    l = *reinterpret_cast<uint32_t*>(&lv);
}

// ---------------- init ------------------------------------------------------
__global__ void k_init() {
    if (threadIdx.x < N_EXP) g_count[threadIdx.x] = 0;
}

// ---------------- conversion: fp32 -> bf16 hi/lo ----------------------------
__global__ void k_conv(const float4* __restrict__ src, int which, int n4) {
    int i = blockIdx.x * 256 + threadIdx.x;
    if (i >= n4) return;
    uint2* hi; uint2* lo;
    switch (which) {
        case 0: hi = (uint2*)cx_hi;  lo = (uint2*)cx_lo;  break;
        case 1: hi = (uint2*)cwg_hi; lo = (uint2*)cwg_lo; break;
        case 2: hi = (uint2*)cwu_hi; lo = (uint2*)cwu_lo; break;
        default:hi = (uint2*)cwd_hi; lo = (uint2*)cwd_lo; break;
    }
    float4 v = src[i];
    uint32_t h0, l0, h1, l1;
    split2(v.x, v.y, h0, l0);
    split2(v.z, v.w, h1, l1);
    hi[i] = make_uint2(h0, h1);
    lo[i] = make_uint2(l0, l1);
}

// ---------------- router ----------------------------------------------------
__global__ void k_router(const float* __restrict__ x,
                         const float* __restrict__ gw) {
    int gid  = blockIdx.x * blockDim.x + threadIdx.x;
    int t    = gid >> 5;
    int lane = gid & 31;
    if (t >= T_TOK) return;

    const float* xr = x + (size_t)t * H_DIM;
    float acc[N_EXP];
#pragma unroll
    for (int e = 0; e < N_EXP; e++) acc[e] = 0.f;

    for (int h = lane; h < H_DIM; h += 32) {
        float xv = xr[h];
#pragma unroll
        for (int e = 0; e < N_EXP; e++) acc[e] += xv * gw[e * H_DIM + h];
    }
#pragma unroll
    for (int e = 0; e < N_EXP; e++) {
#pragma unroll
        for (int o = 16; o > 0; o >>= 1)
            acc[e] += __shfl_xor_sync(0xffffffffu, acc[e], o);
    }

    if (lane == 0) {
        float m = acc[0];
#pragma unroll
        for (int e = 1; e < N_EXP; e++) m = fmaxf(m, acc[e]);
        float p[N_EXP];
        float s = 0.f;
#pragma unroll
        for (int e = 0; e < N_EXP; e++) { p[e] = expf(acc[e] - m); s += p[e]; }
        float inv = 1.f / s;
#pragma unroll
        for (int e = 0; e < N_EXP; e++) p[e] *= inv;

        int e0 = 0;
#pragma unroll
        for (int e = 1; e < N_EXP; e++) if (p[e] > p[e0]) e0 = e;
        int e1 = -1;
#pragma unroll
        for (int e = 0; e < N_EXP; e++) {
            if (e == e0) continue;
            if (e1 < 0 || p[e] > p[e1]) e1 = e;
        }
        float den = p[e0] + p[e1];
        float w0 = p[e0] / den;
        float w1 = p[e1] / den;

        int pos0 = atomicAdd(&g_count[e0], 1);
        g_tok [e0 * T_TOK + pos0] = t;
        g_wt  [e0 * T_TOK + pos0] = w0;
        g_slot[e0 * T_TOK + pos0] = 0;

        int pos1 = atomicAdd(&g_count[e1], 1);
        g_tok [e1 * T_TOK + pos1] = t;
        g_wt  [e1 * T_TOK + pos1] = w1;
        g_slot[e1 * T_TOK + pos1] = 1;
    }
}

// ======================= GEMM1: silu(x Wg^T) * (x Wu^T) =====================
// CTA: 128 tokens x 64 inter. kc=32, 2-stage cp.async. 8 warps: 0-3 gate, 4-7 up.
// smem stage (40960B): Ahi(10240) Alo(10240) Bghi(5120) Bglo(5120) Buhi(5120) Bulo(5120)
#define G1_STG   40960
#define G1_SMEM  (2 * G1_STG + 512)

__device__ __forceinline__ void g1_load(uint32_t sbase, int st, int kt,
                                        int e, int col0, const int* toks_s) {
    const int k0 = kt * 32;
    const uint32_t sb = sbase + st * G1_STG;
    const int tid = threadIdx.x;
#pragma unroll
    for (int j = 0; j < 2; j++) {
        int chunk = tid + j * 256;
        int row = chunk >> 2, c = chunk & 3;
        size_t go = (size_t)toks_s[row] * H_DIM + k0 + c * 8;
        cp16(sb + row * 80 + c * 16, cx_hi + go);
        cp16(sb + 10240 + row * 80 + c * 16, cx_lo + go);
    }
    {
        int row = tid >> 2, c = tid & 3;
        size_t go = ((size_t)(e * I_DIM + col0 + row)) * H_DIM + k0 + c * 8;
        cp16(sb + 20480 + row * 80 + c * 16, cwg_hi + go);
        cp16(sb + 25600 + row * 80 + c * 16, cwg_lo + go);
        cp16(sb + 30720 + row * 80 + c * 16, cwu_hi + go);
        cp16(sb + 35840 + row * 80 + c * 16, cwu_lo + go);
    }
}

__global__ __launch_bounds__(256, 2) void k_gemm1() {
    extern __shared__ char smem[];
    const int e    = blockIdx.z;
    const int n    = g_count[e];
    const int row0 = blockIdx.x * 128;
    if (row0 >= n) return;
    const int col0 = blockIdx.y * 64;
    const int tid  = threadIdx.x;
    const int l    = tid & 31;
    const int w    = tid >> 5;
    const bool isU = (w >= 4);
    const int m0   = (w & 3) * 32;

    int* toks_s = (int*)(smem + 2 * G1_STG);
    if (tid < 128) {
        int r = row0 + tid;
        toks_s[tid] = (r < n) ? g_tok[e * T_TOK + r] : 0;
    }
    __syncthreads();

    const uint32_t sbase = smem_u32(smem);

    float acc[2][8][4];
#pragma unroll
    for (int a = 0; a < 2; a++)
#pragma unroll
        for (int b = 0; b < 8; b++)
#pragma unroll
            for (int c = 0; c < 4; c++) acc[a][b][c] = 0.f;

    const int KT = H_DIM / 32;  // 64
    g1_load(sbase, 0, 0, e, col0, toks_s);
    CP_COMMIT();

    const uint32_t arow = (uint32_t)((l & 7) + ((l >> 3) & 1) * 8);
    const uint32_t brow = (uint32_t)((l & 7) + ((l >> 4) & 1) * 8);

    for (int kt = 0; kt < KT; kt++) {
        if (kt + 1 < KT) { g1_load(sbase, (kt + 1) & 1, kt + 1, e, col0, toks_s); CP_COMMIT(); }
        if (kt + 1 < KT) CP_WAIT(1); else CP_WAIT(0);
        __syncthreads();

        const uint32_t sA  = sbase + (kt & 1) * G1_STG;
        const uint32_t sAl = sA + 10240;
        const uint32_t sB  = sA + (isU ? 30720 : 20480);
        const uint32_t sBl = sB + 5120;

#pragma unroll
        for (int ks = 0; ks < 2; ks++) {
            const uint32_t acol = (uint32_t)(((l >> 4) * 8 + ks * 16) * 2);
            const uint32_t bcol = (uint32_t)((((l >> 3) & 1) * 8 + ks * 16) * 2);
            uint32_t ah[2][4], al[2][4];
            ldm4(ah[0][0], ah[0][1], ah[0][2], ah[0][3], sA  + (m0 + arow) * 80 + acol);
            ldm4(ah[1][0], ah[1][1], ah[1][2], ah[1][3], sA  + (m0 + 16 + arow) * 80 + acol);
            ldm4(al[0][0], al[0][1], al[0][2], al[0][3], sAl + (m0 + arow) * 80 + acol);
            ldm4(al[1][0], al[1][1], al[1][2], al[1][3], sAl + (m0 + 16 + arow) * 80 + acol);
#pragma unroll
            for (int np = 0; np < 4; np++) {
                uint32_t bh[4], bl[4];
                ldm4(bh[0], bh[1], bh[2], bh[3], sB  + (np * 16 + brow) * 80 + bcol);
                ldm4(bl[0], bl[1], bl[2], bl[3], sBl + (np * 16 + brow) * 80 + bcol);
#pragma unroll
                for (int mt = 0; mt < 2; mt++) {
                    mma16816(acc[mt][np * 2 + 0], ah[mt][0], ah[mt][1], ah[mt][2], ah[mt][3], bh[0], bh[1]);
                    mma16816(acc[mt][np * 2 + 1], ah[mt][0], ah[mt][1], ah[mt][2], ah[mt][3], bh[2], bh[3]);
                    mma16816(acc[mt][np * 2 + 0], ah[mt][0], ah[mt][1], ah[mt][2], ah[mt][3], bl[0], bl[1]);
                    mma16816(acc[mt][np * 2 + 1], ah[mt][0], ah[mt][1], ah[mt][2], ah[mt][3], bl[2], bl[3]);
                    mma16816(acc[mt][np * 2 + 0], al[mt][0], al[mt][1], al[mt][2], al[mt][3], bh[0], bh[1]);
                    mma16816(acc[mt][np * 2 + 1], al[mt][0], al[mt][1], al[mt][2], al[mt][3], bh[2], bh[3]);
                }
            }
        }
        __syncthreads();
    }

    // epilogue: U warps -> smem, G warps compute silu(g)*u, split, store bf16 hi/lo
    float* Ub = (float*)smem;   // pitch 72 floats; stage-0 region (last compute used stage 1)
    if (isU) {
#pragma unroll
        for (int mt = 0; mt < 2; mt++)
#pragma unroll
            for (int nt = 0; nt < 8; nt++) {
                int m  = m0 + mt * 16 + (l >> 2);
                int cc = nt * 8 + (l & 3) * 2;
                *(float2*)&Ub[m * 72 + cc]       = make_float2(acc[mt][nt][0], acc[mt][nt][1]);
                *(float2*)&Ub[(m + 8) * 72 + cc] = make_float2(acc[mt][nt][2], acc[mt][nt][3]);
            }
    }
    __syncthreads();
    if (!isU) {
#pragma unroll
        for (int mt = 0; mt < 2; mt++)
#pragma unroll
            for (int nt = 0; nt < 8; nt++) {
                int m  = m0 + mt * 16 + (l >> 2);
                int cc = nt * 8 + (l & 3) * 2;
#pragma unroll
                for (int half = 0; half < 2; half++) {
                    int mm = m + half * 8;
                    int rr = row0 + mm;
                    if (rr < n) {
                        float2 u = *(float2*)&Ub[mm * 72 + cc];
                        float g0 = acc[mt][nt][half * 2 + 0];
                        float g1 = acc[mt][nt][half * 2 + 1];
                        float a0 = g0 / (1.f + __expf(-g0)) * u.x;
                        float a1 = g1 / (1.f + __expf(-g1)) * u.y;
                        uint32_t hw, lw;
                        split2(a0, a1, hw, lw);
                        size_t idx = ((size_t)e * T_TOK + rr) * I_DIM + col0 + cc;
                        *(uint32_t*)(act_hi + idx) = hw;
                        *(uint32_t*)(act_lo + idx) = lw;
                    }
                }
            }
    }
}

// ======================= GEMM2: rw * (act Wd^T) =============================
// CTA: 128 rows x 128 H-cols. kc=32, 2-stage. 8 warps in 4x2 grid, warp 32x64.
// smem stage (40960B): Ahi(10240) Alo(10240) Bhi(10240) Blo(10240)
#define G2_STG   40960
#define G2_SMEM  (2 * G2_STG + 1536)

__device__ __forceinline__ void g2_load(uint32_t sbase, int st, int kt,
                                        int e, int row0, int col0) {
    const int k0 = kt * 32;
    const uint32_t sb = sbase + st * G2_STG;
    const int tid = threadIdx.x;
#pragma unroll
    for (int j = 0; j < 2; j++) {
        int chunk = tid + j * 256;
        int row = chunk >> 2, c = chunk & 3;
        size_t ga = ((size_t)e * T_TOK + row0 + row) * I_DIM + k0 + c * 8;
        cp16(sb + row * 80 + c * 16, act_hi + ga);
        cp16(sb + 10240 + row * 80 + c * 16, act_lo + ga);
        size_t gb = ((size_t)(e * H_DIM + col0 + row)) * I_DIM + k0 + c * 8;
        cp16(sb + 20480 + row * 80 + c * 16, cwd_hi + gb);
        cp16(sb + 30720 + row * 80 + c * 16, cwd_lo + gb);
    }
}

__global__ __launch_bounds__(256, 2) void k_gemm2() {
    extern __shared__ char smem[];
    const int e    = blockIdx.z;
    const int n    = g_count[e];
    const int row0 = blockIdx.x * 128;
    if (row0 >= n) return;
    const int col0 = blockIdx.y * 128;
    const int tid  = threadIdx.x;
    const int l    = tid & 31;
    const int w    = tid >> 5;
    const int m0   = (w & 3) * 32;
    const int nw0  = (w >> 2) * 64;

    int*   toks_s = (int*)  (smem + 2 * G2_STG);
    float* ws_s   = (float*)(smem + 2 * G2_STG + 512);
    int*   ks_s   = (int*)  (smem + 2 * G2_STG + 1024);
    if (tid < 128) {
        int r = row0 + tid;
        if (r < n) {
            toks_s[tid] = g_tok [e * T_TOK + r];
            ws_s[tid]   = g_wt  [e * T_TOK + r];
            ks_s[tid]   = g_slot[e * T_TOK + r];
        } else { toks_s[tid] = 0; ws_s[tid] = 0.f; ks_s[tid] = 0; }
    }
    __syncthreads();

    const uint32_t sbase = smem_u32(smem);

    float acc[2][8][4];
#pragma unroll
    for (int a = 0; a < 2; a++)
#pragma unroll
        for (int b = 0; b < 8; b++)
#pragma unroll
            for (int c = 0; c < 4; c++) acc[a][b][c] = 0.f;

    const int KT = I_DIM / 32;  // 32
    g2_load(sbase, 0, 0, e, row0, col0);
    CP_COMMIT();

    const uint32_t arow = (uint32_t)((l & 7) + ((l >> 3) & 1) * 8);
    const uint32_t brow = (uint32_t)((l & 7) + ((l >> 4) & 1) * 8);

    for (int kt = 0; kt < KT; kt++) {
        if (kt + 1 < KT) { g2_load(sbase, (kt + 1) & 1, kt + 1, e, row0, col0); CP_COMMIT(); }
        if (kt + 1 < KT) CP_WAIT(1); else CP_WAIT(0);
        __syncthreads();

        const uint32_t sA  = sbase + (kt & 1) * G2_STG;
        const uint32_t sAl = sA + 10240;
        const uint32_t sB  = sA + 20480;
        const uint32_t sBl = sA + 30720;

#pragma unroll
        for (int ks = 0; ks < 2; ks++) {
            const uint32_t acol = (uint32_t)(((l >> 4) * 8 + ks * 16) * 2);
            const uint32_t bcol = (uint32_t)((((l >> 3) & 1) * 8 + ks * 16) * 2);
            uint32_t ah[2][4], al[2][4];
            ldm4(ah[0][0], ah[0][1], ah[0][2], ah[0][3], sA  + (m0 + arow) * 80 + acol);
            ldm4(ah[1][0], ah[1][1], ah[1][2], ah[1][3], sA  + (m0 + 16 + arow) * 80 + acol);
            ldm4(al[0][0], al[0][1], al[0][2], al[0][3], sAl + (m0 + arow) * 80 + acol);
            ldm4(al[1][0], al[1][1], al[1][2], al[1][3], sAl + (m0 + 16 + arow) * 80 + acol);
#pragma unroll
            for (int np = 0; np < 4; np++) {
                uint32_t bh[4], bl[4];
                ldm4(bh[0], bh[1], bh[2], bh[3], sB  + (nw0 + np * 16 + brow) * 80 + bcol);
                ldm4(bl[0], bl[1], bl[2], bl[3], sBl + (nw0 + np * 16 + brow) * 80 + bcol);
#pragma unroll
                for (int mt = 0; mt < 2; mt++) {
                    mma16816(acc[mt][np * 2 + 0], ah[mt][0], ah[mt][1], ah[mt][2], ah[mt][3], bh[0], bh[1]);
                    mma16816(acc[mt][np * 2 + 1], ah[mt][0], ah[mt][1], ah[mt][2], ah[mt][3], bh[2], bh[3]);
                    mma16816(acc[mt][np * 2 + 0], ah[mt][0], ah[mt][1], ah[mt][2], ah[mt][3], bl[0], bl[1]);
                    mma16816(acc[mt][np * 2 + 1], ah[mt][0], ah[mt][1], ah[mt][2], ah[mt][3], bl[2], bl[3]);
                    mma16816(acc[mt][np * 2 + 0], al[mt][0], al[mt][1], al[mt][2], al[mt][3], bh[0], bh[1]);
                    mma16816(acc[mt][np * 2 + 1], al[mt][0], al[mt][1], al[mt][2], al[mt][3], bh[2], bh[3]);
                }
            }
        }
        __syncthreads();
    }

    // epilogue: scale by routing weight, write fp32 partials
#pragma unroll
    for (int mt = 0; mt < 2; mt++)
#pragma unroll
        for (int nt = 0; nt < 8; nt++) {
            int m  = m0 + mt * 16 + (l >> 2);
            int cc = nw0 + nt * 8 + (l & 3) * 2;
#pragma unroll
            for (int half = 0; half < 2; half++) {
                int mm = m + half * 8;
                if (row0 + mm < n) {
                    int   t  = toks_s[mm];
                    int   k  = ks_s[mm];
                    float wt = ws_s[mm];
                    float2 v = make_float2(acc[mt][nt][half * 2 + 0] * wt,
                                           acc[mt][nt][half * 2 + 1] * wt);
                    *(float2*)&g_part[((size_t)t * 2 + k) * H_DIM + col0 + cc] = v;
                }
            }
        }
}

// ---------------- combine ----------------------------------------------------
__global__ void k_combine(float* __restrict__ out) {
    int i = blockIdx.x * 256 + threadIdx.x;
    if (i >= T_TOK * H_DIM) return;
    int t = i >> 11;
    int h = i & (H_DIM - 1);
    out[i] = g_part[((size_t)t * 2 + 0) * H_DIM + h] +
             g_part[((size_t)t * 2 + 1) * H_DIM + h];
}

// ---------------- launch -----------------------------------------------------
extern "C" void kernel_launch(void* const* d_in, const int* in_sizes, int n_in,
                              void* d_out, int out_size) {
    const float* x  = (const float*)d_in[0];
    const float* gw = (const float*)d_in[1];
    const float* wg = (const float*)d_in[2];
    const float* wu = (const float*)d_in[3];
    const float* wd = (const float*)d_in[4];
    float* out = (float*)d_out;

    static int attr_done = 0;
    if (!attr_done) {
        cudaFuncSetAttribute(k_gemm1, cudaFuncAttributeMaxDynamicSharedMemorySize, G1_SMEM);
        cudaFuncSetAttribute(k_gemm2, cudaFuncAttributeMaxDynamicSharedMemorySize, G2_SMEM);
        attr_done = 1;
    }

    k_init<<<1, 32>>>();
    k_router<<<(T_TOK * 32) / 256, 256>>>(x, gw);
    k_conv<<<(T_TOK * H_DIM / 4 + 255) / 256, 256>>>((const float4*)x,  0, T_TOK * H_DIM / 4);
    k_conv<<<(N_EXP * I_DIM * H_DIM / 4 + 255) / 256, 256>>>((const float4*)wg, 1, N_EXP * I_DIM * H_DIM / 4);
    k_conv<<<(N_EXP * I_DIM * H_DIM / 4 + 255) / 256, 256>>>((const float4*)wu, 2, N_EXP * I_DIM * H_DIM / 4);
    k_conv<<<(N_EXP * H_DIM * I_DIM / 4 + 255) / 256, 256>>>((const float4*)wd, 3, N_EXP * H_DIM * I_DIM / 4);
    k_gemm1<<<dim3(T_TOK / 128, I_DIM / 64, N_EXP), 256, G1_SMEM>>>();
    k_gemm2<<<dim3(T_TOK / 128, H_DIM / 128, N_EXP), 256, G2_SMEM>>>();
    k_combine<<<(T_TOK * H_DIM + 255) / 256, 256>>>(out);
}

// round 4
// speedup vs baseline: 3.8684x; 1.4133x over previous
#include <cuda_runtime.h>
#include <cuda_fp16.h>
#include <math.h>
#include <stdint.h>

#define T_TOK 4096
#define H_DIM 2048
#define I_DIM 1024
#define N_EXP 8

// ---------------- scratch (static device globals; no allocation) ------------
__device__ int   g_count[N_EXP];
__device__ int   g_tok [N_EXP * T_TOK];
__device__ float g_wt  [N_EXP * T_TOK];
__device__ int   g_slot[N_EXP * T_TOK];

// converted fp16 operands: A-side split hi/lo, B-side (weights) hi only
__device__ __half cx_hi [(size_t)T_TOK * H_DIM];
__device__ __half cx_lo [(size_t)T_TOK * H_DIM];
__device__ __half cwg_hi[(size_t)N_EXP * I_DIM * H_DIM];
__device__ __half cwu_hi[(size_t)N_EXP * I_DIM * H_DIM];
__device__ __half cwd_hi[(size_t)N_EXP * H_DIM * I_DIM];
__device__ __half act_hi[(size_t)N_EXP * T_TOK * I_DIM];
__device__ __half act_lo[(size_t)N_EXP * T_TOK * I_DIM];

// ======================= helpers ============================================
__device__ __forceinline__ uint32_t smem_u32(const void* p) {
    uint32_t a;
    asm("{ .reg .u64 t; cvta.to.shared.u64 t, %1; cvt.u32.u64 %0, t; }"
        : "=r"(a) : "l"(p));
    return a;
}

__device__ __forceinline__ void cp16(uint32_t s, const void* g) {
    asm volatile("cp.async.cg.shared.global [%0], [%1], 16;"
                 :: "r"(s), "l"(g) : "memory");
}
#define CP_COMMIT() asm volatile("cp.async.commit_group;" ::: "memory")
#define CP_WAIT(n)  asm volatile("cp.async.wait_group %0;" :: "n"(n) : "memory")

__device__ __forceinline__ void ldm4(uint32_t& r0, uint32_t& r1,
                                     uint32_t& r2, uint32_t& r3, uint32_t a) {
    asm volatile("ldmatrix.sync.aligned.m8n8.x4.shared.b16 {%0,%1,%2,%3}, [%4];"
                 : "=r"(r0), "=r"(r1), "=r"(r2), "=r"(r3) : "r"(a));
}

__device__ __forceinline__ void mma16816(float* c, uint32_t a0, uint32_t a1,
                                         uint32_t a2, uint32_t a3,
                                         uint32_t b0, uint32_t b1) {
    asm volatile(
        "mma.sync.aligned.m16n8k16.row.col.f32.f16.f16.f32 "
        "{%0,%1,%2,%3}, {%4,%5,%6,%7}, {%8,%9}, {%0,%1,%2,%3};"
        : "+f"(c[0]), "+f"(c[1]), "+f"(c[2]), "+f"(c[3])
        : "r"(a0), "r"(a1), "r"(a2), "r"(a3), "r"(b0), "r"(b1));
}

// split two fp32 into fp16 hi pair + lo pair (packed half2)
__device__ __forceinline__ void split2h(float a, float b, uint32_t& h, uint32_t& l) {
    __half2 hv = __floats2half2_rn(a, b);
    float2 hf = __half22float2(hv);
    __half2 lv = __floats2half2_rn(a - hf.x, b - hf.y);
    h = *reinterpret_cast<uint32_t*>(&hv);
    l = *reinterpret_cast<uint32_t*>(&lv);
}
__device__ __forceinline__ uint32_t pack2h(float a, float b) {
    __half2 hv = __floats2half2_rn(a, b);
    return *reinterpret_cast<uint32_t*>(&hv);
}

// ---------------- init ------------------------------------------------------
__global__ void k_init() {
    if (threadIdx.x < N_EXP) g_count[threadIdx.x] = 0;
}

__global__ void k_zero(float4* __restrict__ out) {
    int i = blockIdx.x * 256 + threadIdx.x;
    if (i < T_TOK * H_DIM / 4) out[i] = make_float4(0.f, 0.f, 0.f, 0.f);
}

// ---------------- conversion (single launch): x -> hi/lo; weights -> hi -----
#define N4_X (T_TOK * H_DIM / 4)                 // 2M float4
#define N4_W (N_EXP * I_DIM * H_DIM / 4)         // 4M float4 each
__global__ void k_conv(const float4* __restrict__ x,  const float4* __restrict__ wg,
                       const float4* __restrict__ wu, const float4* __restrict__ wd) {
    int i = blockIdx.x * 256 + threadIdx.x;
    if (i < N4_X) {
        float4 v = x[i];
        uint32_t h0, l0, h1, l1;
        split2h(v.x, v.y, h0, l0);
        split2h(v.z, v.w, h1, l1);
        ((uint2*)cx_hi)[i] = make_uint2(h0, h1);
        ((uint2*)cx_lo)[i] = make_uint2(l0, l1);
        return;
    }
    int j = i - N4_X;
    const float4* src;
    uint2* dst;
    if (j < N4_W)          { src = wg; dst = (uint2*)cwg_hi; }
    else if (j < 2 * N4_W) { src = wu; dst = (uint2*)cwu_hi; j -= N4_W; }
    else if (j < 3 * N4_W) { src = wd; dst = (uint2*)cwd_hi; j -= 2 * N4_W; }
    else return;
    float4 v = src[j];
    dst[j] = make_uint2(pack2h(v.x, v.y), pack2h(v.z, v.w));
}

// ---------------- router ----------------------------------------------------
__global__ void k_router(const float* __restrict__ x,
                         const float* __restrict__ gw) {
    int gid  = blockIdx.x * blockDim.x + threadIdx.x;
    int t    = gid >> 5;
    int lane = gid & 31;
    if (t >= T_TOK) return;

    const float* xr = x + (size_t)t * H_DIM;
    float acc[N_EXP];
#pragma unroll
    for (int e = 0; e < N_EXP; e++) acc[e] = 0.f;

    for (int h = lane; h < H_DIM; h += 32) {
        float xv = xr[h];
#pragma unroll
        for (int e = 0; e < N_EXP; e++) acc[e] += xv * gw[e * H_DIM + h];
    }
#pragma unroll
    for (int e = 0; e < N_EXP; e++) {
#pragma unroll
        for (int o = 16; o > 0; o >>= 1)
            acc[e] += __shfl_xor_sync(0xffffffffu, acc[e], o);
    }

    if (lane == 0) {
        float m = acc[0];
#pragma unroll
        for (int e = 1; e < N_EXP; e++) m = fmaxf(m, acc[e]);
        float p[N_EXP];
        float s = 0.f;
#pragma unroll
        for (int e = 0; e < N_EXP; e++) { p[e] = expf(acc[e] - m); s += p[e]; }
        float inv = 1.f / s;
#pragma unroll
        for (int e = 0; e < N_EXP; e++) p[e] *= inv;

        int e0 = 0;
#pragma unroll
        for (int e = 1; e < N_EXP; e++) if (p[e] > p[e0]) e0 = e;
        int e1 = -1;
#pragma unroll
        for (int e = 0; e < N_EXP; e++) {
            if (e == e0) continue;
            if (e1 < 0 || p[e] > p[e1]) e1 = e;
        }
        float den = p[e0] + p[e1];
        float w0 = p[e0] / den;
        float w1 = p[e1] / den;

        int pos0 = atomicAdd(&g_count[e0], 1);
        g_tok [e0 * T_TOK + pos0] = t;
        g_wt  [e0 * T_TOK + pos0] = w0;
        g_slot[e0 * T_TOK + pos0] = 0;

        int pos1 = atomicAdd(&g_count[e1], 1);
        g_tok [e1 * T_TOK + pos1] = t;
        g_wt  [e1 * T_TOK + pos1] = w1;
        g_slot[e1 * T_TOK + pos1] = 1;
    }
}

// ======================= GEMM1: silu(x Wg^T) * (x Wu^T) =====================
// CTA: 128 tokens x 64 inter. kc=32, 2-stage cp.async. 8 warps: 0-3 gate, 4-7 up.
// stage (30720B): Ahi(10240) Alo(10240) Bg_hi(5120) Bu_hi(5120)
#define G1_STG   30720
#define G1_SMEM  (2 * G1_STG + 512)

__device__ __forceinline__ void g1_load(uint32_t sbase, int st, int kt,
                                        int e, int col0, const int* toks_s) {
    const int k0 = kt * 32;
    const uint32_t sb = sbase + st * G1_STG;
    const int tid = threadIdx.x;
#pragma unroll
    for (int j = 0; j < 2; j++) {
        int chunk = tid + j * 256;
        int row = chunk >> 2, c = chunk & 3;
        size_t go = (size_t)toks_s[row] * H_DIM + k0 + c * 8;
        cp16(sb + row * 80 + c * 16, cx_hi + go);
        cp16(sb + 10240 + row * 80 + c * 16, cx_lo + go);
    }
    {
        int row = tid >> 2, c = tid & 3;
        size_t go = ((size_t)(e * I_DIM + col0 + row)) * H_DIM + k0 + c * 8;
        cp16(sb + 20480 + row * 80 + c * 16, cwg_hi + go);
        cp16(sb + 25600 + row * 80 + c * 16, cwu_hi + go);
    }
}

__global__ __launch_bounds__(256, 2) void k_gemm1() {
    extern __shared__ char smem[];
    const int e    = blockIdx.z;
    const int n    = g_count[e];
    const int row0 = blockIdx.x * 128;
    if (row0 >= n) return;
    const int col0 = blockIdx.y * 64;
    const int tid  = threadIdx.x;
    const int l    = tid & 31;
    const int w    = tid >> 5;
    const bool isU = (w >= 4);
    const int m0   = (w & 3) * 32;

    int* toks_s = (int*)(smem + 2 * G1_STG);
    if (tid < 128) {
        int r = row0 + tid;
        toks_s[tid] = (r < n) ? g_tok[e * T_TOK + r] : 0;
    }
    __syncthreads();

    const uint32_t sbase = smem_u32(smem);

    float acc[2][8][4];
#pragma unroll
    for (int a = 0; a < 2; a++)
#pragma unroll
        for (int b = 0; b < 8; b++)
#pragma unroll
            for (int c = 0; c < 4; c++) acc[a][b][c] = 0.f;

    const int KT = H_DIM / 32;  // 64
    g1_load(sbase, 0, 0, e, col0, toks_s);
    CP_COMMIT();

    const uint32_t arow = (uint32_t)((l & 7) + ((l >> 3) & 1) * 8);
    const uint32_t brow = (uint32_t)((l & 7) + ((l >> 4) & 1) * 8);

    for (int kt = 0; kt < KT; kt++) {
        if (kt + 1 < KT) { g1_load(sbase, (kt + 1) & 1, kt + 1, e, col0, toks_s); CP_COMMIT(); }
        if (kt + 1 < KT) CP_WAIT(1); else CP_WAIT(0);
        __syncthreads();

        const uint32_t sA  = sbase + (kt & 1) * G1_STG;
        const uint32_t sAl = sA + 10240;
        const uint32_t sB  = sA + (isU ? 25600 : 20480);

#pragma unroll
        for (int ks = 0; ks < 2; ks++) {
            const uint32_t acol = (uint32_t)(((l >> 4) * 8 + ks * 16) * 2);
            const uint32_t bcol = (uint32_t)((((l >> 3) & 1) * 8 + ks * 16) * 2);
            uint32_t ah[2][4], al[2][4];
            ldm4(ah[0][0], ah[0][1], ah[0][2], ah[0][3], sA  + (m0 + arow) * 80 + acol);
            ldm4(ah[1][0], ah[1][1], ah[1][2], ah[1][3], sA  + (m0 + 16 + arow) * 80 + acol);
            ldm4(al[0][0], al[0][1], al[0][2], al[0][3], sAl + (m0 + arow) * 80 + acol);
            ldm4(al[1][0], al[1][1], al[1][2], al[1][3], sAl + (m0 + 16 + arow) * 80 + acol);
#pragma unroll
            for (int np = 0; np < 4; np++) {
                uint32_t bh[4];
                ldm4(bh[0], bh[1], bh[2], bh[3], sB + (np * 16 + brow) * 80 + bcol);
#pragma unroll
                for (int mt = 0; mt < 2; mt++) {
                    mma16816(acc[mt][np * 2 + 0], ah[mt][0], ah[mt][1], ah[mt][2], ah[mt][3], bh[0], bh[1]);
                    mma16816(acc[mt][np * 2 + 1], ah[mt][0], ah[mt][1], ah[mt][2], ah[mt][3], bh[2], bh[3]);
                    mma16816(acc[mt][np * 2 + 0], al[mt][0], al[mt][1], al[mt][2], al[mt][3], bh[0], bh[1]);
                    mma16816(acc[mt][np * 2 + 1], al[mt][0], al[mt][1], al[mt][2], al[mt][3], bh[2], bh[3]);
                }
            }
        }
        __syncthreads();
    }

    // epilogue: U warps -> smem, G warps compute silu(g)*u, split, store fp16 hi/lo
    float* Ub = (float*)smem;   // pitch 72 floats
    if (isU) {
#pragma unroll
        for (int mt = 0; mt < 2; mt++)
#pragma unroll
            for (int nt = 0; nt < 8; nt++) {
                int m  = m0 + mt * 16 + (l >> 2);
                int cc = nt * 8 + (l & 3) * 2;
                *(float2*)&Ub[m * 72 + cc]       = make_float2(acc[mt][nt][0], acc[mt][nt][1]);
                *(float2*)&Ub[(m + 8) * 72 + cc] = make_float2(acc[mt][nt][2], acc[mt][nt][3]);
            }
    }
    __syncthreads();
    if (!isU) {
#pragma unroll
        for (int mt = 0; mt < 2; mt++)
#pragma unroll
            for (int nt = 0; nt < 8; nt++) {
                int m  = m0 + mt * 16 + (l >> 2);
                int cc = nt * 8 + (l & 3) * 2;
#pragma unroll
                for (int half = 0; half < 2; half++) {
                    int mm = m + half * 8;
                    int rr = row0 + mm;
                    if (rr < n) {
                        float2 u = *(float2*)&Ub[mm * 72 + cc];
                        float g0 = acc[mt][nt][half * 2 + 0];
                        float g1 = acc[mt][nt][half * 2 + 1];
                        float a0 = g0 / (1.f + __expf(-g0)) * u.x;
                        float a1 = g1 / (1.f + __expf(-g1)) * u.y;
                        uint32_t hw, lw;
                        split2h(a0, a1, hw, lw);
                        size_t idx = ((size_t)e * T_TOK + rr) * I_DIM + col0 + cc;
                        *(uint32_t*)(act_hi + idx) = hw;
                        *(uint32_t*)(act_lo + idx) = lw;
                    }
                }
            }
    }
}

// ======================= GEMM2: out += rw * (act Wd^T) ======================
// CTA: 128 rows x 128 H-cols. kc=32, 2-stage. 8 warps in 4x2 grid, warp 32x64.
// stage (30720B): Ahi(10240) Alo(10240) B_hi(10240)
#define G2_STG   30720
#define G2_SMEM  (2 * G2_STG + 1536)

__device__ __forceinline__ void g2_load(uint32_t sbase, int st, int kt,
                                        int e, int row0, int col0) {
    const int k0 = kt * 32;
    const uint32_t sb = sbase + st * G2_STG;
    const int tid = threadIdx.x;
#pragma unroll
    for (int j = 0; j < 2; j++) {
        int chunk = tid + j * 256;
        int row = chunk >> 2, c = chunk & 3;
        size_t ga = ((size_t)e * T_TOK + row0 + row) * I_DIM + k0 + c * 8;
        cp16(sb + row * 80 + c * 16, act_hi + ga);
        cp16(sb + 10240 + row * 80 + c * 16, act_lo + ga);
        size_t gb = ((size_t)(e * H_DIM + col0 + row)) * I_DIM + k0 + c * 8;
        cp16(sb + 20480 + row * 80 + c * 16, cwd_hi + gb);
    }
}

__global__ __launch_bounds__(256, 2) void k_gemm2(float* __restrict__ out) {
    extern __shared__ char smem[];
    const int e    = blockIdx.z;
    const int n    = g_count[e];
    const int row0 = blockIdx.x * 128;
    if (row0 >= n) return;
    const int col0 = blockIdx.y * 128;
    const int tid  = threadIdx.x;
    const int l    = tid & 31;
    const int w    = tid >> 5;
    const int m0   = (w & 3) * 32;
    const int nw0  = (w >> 2) * 64;

    int*   toks_s = (int*)  (smem + 2 * G2_STG);
    float* ws_s   = (float*)(smem + 2 * G2_STG + 512);
    if (tid < 128) {
        int r = row0 + tid;
        if (r < n) {
            toks_s[tid] = g_tok[e * T_TOK + r];
            ws_s[tid]   = g_wt [e * T_TOK + r];
        } else { toks_s[tid] = 0; ws_s[tid] = 0.f; }
    }
    __syncthreads();

    const uint32_t sbase = smem_u32(smem);

    float acc[2][8][4];
#pragma unroll
    for (int a = 0; a < 2; a++)
#pragma unroll
        for (int b = 0; b < 8; b++)
#pragma unroll
            for (int c = 0; c < 4; c++) acc[a][b][c] = 0.f;

    const int KT = I_DIM / 32;  // 32
    g2_load(sbase, 0, 0, e, row0, col0);
    CP_COMMIT();

    const uint32_t arow = (uint32_t)((l & 7) + ((l >> 3) & 1) * 8);
    const uint32_t brow = (uint32_t)((l & 7) + ((l >> 4) & 1) * 8);

    for (int kt = 0; kt < KT; kt++) {
        if (kt + 1 < KT) { g2_load(sbase, (kt + 1) & 1, kt + 1, e, row0, col0); CP_COMMIT(); }
        if (kt + 1 < KT) CP_WAIT(1); else CP_WAIT(0);
        __syncthreads();

        const uint32_t sA  = sbase + (kt & 1) * G2_STG;
        const uint32_t sAl = sA + 10240;
        const uint32_t sB  = sA + 20480;

#pragma unroll
        for (int ks = 0; ks < 2; ks++) {
            const uint32_t acol = (uint32_t)(((l >> 4) * 8 + ks * 16) * 2);
            const uint32_t bcol = (uint32_t)((((l >> 3) & 1) * 8 + ks * 16) * 2);
            uint32_t ah[2][4], al[2][4];
            ldm4(ah[0][0], ah[0][1], ah[0][2], ah[0][3], sA  + (m0 + arow) * 80 + acol);
            ldm4(ah[1][0], ah[1][1], ah[1][2], ah[1][3], sA  + (m0 + 16 + arow) * 80 + acol);
            ldm4(al[0][0], al[0][1], al[0][2], al[0][3], sAl + (m0 + arow) * 80 + acol);
            ldm4(al[1][0], al[1][1], al[1][2], al[1][3], sAl + (m0 + 16 + arow) * 80 + acol);
#pragma unroll
            for (int np = 0; np < 4; np++) {
                uint32_t bh[4];
                ldm4(bh[0], bh[1], bh[2], bh[3], sB + (nw0 + np * 16 + brow) * 80 + bcol);
#pragma unroll
                for (int mt = 0; mt < 2; mt++) {
                    mma16816(acc[mt][np * 2 + 0], ah[mt][0], ah[mt][1], ah[mt][2], ah[mt][3], bh[0], bh[1]);
                    mma16816(acc[mt][np * 2 + 1], ah[mt][0], ah[mt][1], ah[mt][2], ah[mt][3], bh[2], bh[3]);
                    mma16816(acc[mt][np * 2 + 0], al[mt][0], al[mt][1], al[mt][2], al[mt][3], bh[0], bh[1]);
                    mma16816(acc[mt][np * 2 + 1], al[mt][0], al[mt][1], al[mt][2], al[mt][3], bh[2], bh[3]);
                }
            }
        }
        __syncthreads();
    }

    // epilogue: scale by routing weight, atomic-add into out (2 addends/elem -> deterministic)
#pragma unroll
    for (int mt = 0; mt < 2; mt++)
#pragma unroll
        for (int nt = 0; nt < 8; nt++) {
            int m  = m0 + mt * 16 + (l >> 2);
            int cc = nw0 + nt * 8 + (l & 3) * 2;
#pragma unroll
            for (int half = 0; half < 2; half++) {
                int mm = m + half * 8;
                if (row0 + mm < n) {
                    int   t  = toks_s[mm];
                    float wt = ws_s[mm];
                    float* dst = out + (size_t)t * H_DIM + col0 + cc;
                    atomicAdd(dst + 0, acc[mt][nt][half * 2 + 0] * wt);
                    atomicAdd(dst + 1, acc[mt][nt][half * 2 + 1] * wt);
                }
            }
        }
}

// ---------------- launch -----------------------------------------------------
extern "C" void kernel_launch(void* const* d_in, const int* in_sizes, int n_in,
                              void* d_out, int out_size) {
    const float* x  = (const float*)d_in[0];
    const float* gw = (const float*)d_in[1];
    const float* wg = (const float*)d_in[2];
    const float* wu = (const float*)d_in[3];
    const float* wd = (const float*)d_in[4];
    float* out = (float*)d_out;

    static int attr_done = 0;
    if (!attr_done) {
        cudaFuncSetAttribute(k_gemm1, cudaFuncAttributeMaxDynamicSharedMemorySize, G1_SMEM);
        cudaFuncSetAttribute(k_gemm2, cudaFuncAttributeMaxDynamicSharedMemorySize, G2_SMEM);
        attr_done = 1;
    }

    k_init<<<1, 32>>>();
    k_router<<<(T_TOK * 32) / 256, 256>>>(x, gw);
    k_conv<<<(N4_X + 3 * N4_W + 255) / 256, 256>>>((const float4*)x, (const float4*)wg,
                                                   (const float4*)wu, (const float4*)wd);
    k_zero<<<(T_TOK * H_DIM / 4 + 255) / 256, 256>>>((float4*)out);
    k_gemm1<<<dim3(T_TOK / 128, I_DIM / 64, N_EXP), 256, G1_SMEM>>>();
    k_gemm2<<<dim3(T_TOK / 128, H_DIM / 128, N_EXP), 256, G2_SMEM>>>(out);
}

// round 5
// speedup vs baseline: 4.2953x; 1.1104x over previous
#include <cuda_runtime.h>
#include <cuda_fp16.h>
#include <math.h>
#include <stdint.h>

#define T_TOK 4096
#define H_DIM 2048
#define I_DIM 1024
#define N_EXP 8

// ---------------- scratch (static device globals; no allocation) ------------
__device__ int   g_count[N_EXP];
__device__ int   g_tok [N_EXP * T_TOK];
__device__ float g_wt  [N_EXP * T_TOK];
__device__ int   g_slot[N_EXP * T_TOK];

// converted fp16 operands: x split hi/lo, weights hi only, act hi only
__device__ __half cx_hi [(size_t)T_TOK * H_DIM];
__device__ __half cx_lo [(size_t)T_TOK * H_DIM];
__device__ __half cwg_hi[(size_t)N_EXP * I_DIM * H_DIM];
__device__ __half cwu_hi[(size_t)N_EXP * I_DIM * H_DIM];
__device__ __half cwd_hi[(size_t)N_EXP * H_DIM * I_DIM];
__device__ __half act_hi[(size_t)N_EXP * T_TOK * I_DIM];

// ======================= helpers ============================================
__device__ __forceinline__ uint32_t smem_u32(const void* p) {
    uint32_t a;
    asm("{ .reg .u64 t; cvta.to.shared.u64 t, %1; cvt.u32.u64 %0, t; }"
        : "=r"(a) : "l"(p));
    return a;
}

__device__ __forceinline__ void cp16(uint32_t s, const void* g) {
    asm volatile("cp.async.cg.shared.global [%0], [%1], 16;"
                 :: "r"(s), "l"(g) : "memory");
}
#define CP_COMMIT() asm volatile("cp.async.commit_group;" ::: "memory")
#define CP_WAIT(n)  asm volatile("cp.async.wait_group %0;" :: "n"(n) : "memory")

__device__ __forceinline__ void ldm4(uint32_t& r0, uint32_t& r1,
                                     uint32_t& r2, uint32_t& r3, uint32_t a) {
    asm volatile("ldmatrix.sync.aligned.m8n8.x4.shared.b16 {%0,%1,%2,%3}, [%4];"
                 : "=r"(r0), "=r"(r1), "=r"(r2), "=r"(r3) : "r"(a));
}

__device__ __forceinline__ void mma16816(float* c, uint32_t a0, uint32_t a1,
                                         uint32_t a2, uint32_t a3,
                                         uint32_t b0, uint32_t b1) {
    asm volatile(
        "mma.sync.aligned.m16n8k16.row.col.f32.f16.f16.f32 "
        "{%0,%1,%2,%3}, {%4,%5,%6,%7}, {%8,%9}, {%0,%1,%2,%3};"
        : "+f"(c[0]), "+f"(c[1]), "+f"(c[2]), "+f"(c[3])
        : "r"(a0), "r"(a1), "r"(a2), "r"(a3), "r"(b0), "r"(b1));
}

// split two fp32 into fp16 hi pair + lo pair (packed half2)
__device__ __forceinline__ void split2h(float a, float b, uint32_t& h, uint32_t& l) {
    __half2 hv = __floats2half2_rn(a, b);
    float2 hf = __half22float2(hv);
    __half2 lv = __floats2half2_rn(a - hf.x, b - hf.y);
    h = *reinterpret_cast<uint32_t*>(&hv);
    l = *reinterpret_cast<uint32_t*>(&lv);
}
__device__ __forceinline__ uint32_t pack2h(float a, float b) {
    __half2 hv = __floats2half2_rn(a, b);
    return *reinterpret_cast<uint32_t*>(&hv);
}

// ---------------- init ------------------------------------------------------
__global__ void k_init() {
    if (threadIdx.x < N_EXP) g_count[threadIdx.x] = 0;
}

__global__ void k_zero(float4* __restrict__ out) {
    int i = blockIdx.x * 256 + threadIdx.x;
    if (i < T_TOK * H_DIM / 4) out[i] = make_float4(0.f, 0.f, 0.f, 0.f);
}

// ---------------- conversion (single launch): x -> hi/lo; weights -> hi -----
#define N4_X (T_TOK * H_DIM / 4)                 // 2M float4
#define N4_W (N_EXP * I_DIM * H_DIM / 4)         // 4M float4 each
__global__ void k_conv(const float4* __restrict__ x,  const float4* __restrict__ wg,
                       const float4* __restrict__ wu, const float4* __restrict__ wd) {
    int i = blockIdx.x * 256 + threadIdx.x;
    if (i < N4_X) {
        float4 v = x[i];
        uint32_t h0, l0, h1, l1;
        split2h(v.x, v.y, h0, l0);
        split2h(v.z, v.w, h1, l1);
        ((uint2*)cx_hi)[i] = make_uint2(h0, h1);
        ((uint2*)cx_lo)[i] = make_uint2(l0, l1);
        return;
    }
    int j = i - N4_X;
    const float4* src;
    uint2* dst;
    if (j < N4_W)          { src = wg; dst = (uint2*)cwg_hi; }
    else if (j < 2 * N4_W) { src = wu; dst = (uint2*)cwu_hi; j -= N4_W; }
    else if (j < 3 * N4_W) { src = wd; dst = (uint2*)cwd_hi; j -= 2 * N4_W; }
    else return;
    float4 v = src[j];
    dst[j] = make_uint2(pack2h(v.x, v.y), pack2h(v.z, v.w));
}

// ---------------- router ----------------------------------------------------
__global__ void k_router(const float* __restrict__ x,
                         const float* __restrict__ gw) {
    int gid  = blockIdx.x * blockDim.x + threadIdx.x;
    int t    = gid >> 5;
    int lane = gid & 31;
    if (t >= T_TOK) return;

    const float* xr = x + (size_t)t * H_DIM;
    float acc[N_EXP];
#pragma unroll
    for (int e = 0; e < N_EXP; e++) acc[e] = 0.f;

    for (int h = lane; h < H_DIM; h += 32) {
        float xv = xr[h];
#pragma unroll
        for (int e = 0; e < N_EXP; e++) acc[e] += xv * gw[e * H_DIM + h];
    }
#pragma unroll
    for (int e = 0; e < N_EXP; e++) {
#pragma unroll
        for (int o = 16; o > 0; o >>= 1)
            acc[e] += __shfl_xor_sync(0xffffffffu, acc[e], o);
    }

    if (lane == 0) {
        float m = acc[0];
#pragma unroll
        for (int e = 1; e < N_EXP; e++) m = fmaxf(m, acc[e]);
        float p[N_EXP];
        float s = 0.f;
#pragma unroll
        for (int e = 0; e < N_EXP; e++) { p[e] = expf(acc[e] - m); s += p[e]; }
        float inv = 1.f / s;
#pragma unroll
        for (int e = 0; e < N_EXP; e++) p[e] *= inv;

        int e0 = 0;
#pragma unroll
        for (int e = 1; e < N_EXP; e++) if (p[e] > p[e0]) e0 = e;
        int e1 = -1;
#pragma unroll
        for (int e = 0; e < N_EXP; e++) {
            if (e == e0) continue;
            if (e1 < 0 || p[e] > p[e1]) e1 = e;
        }
        float den = p[e0] + p[e1];
        float w0 = p[e0] / den;
        float w1 = p[e1] / den;

        int pos0 = atomicAdd(&g_count[e0], 1);
        g_tok [e0 * T_TOK + pos0] = t;
        g_wt  [e0 * T_TOK + pos0] = w0;
        g_slot[e0 * T_TOK + pos0] = 0;

        int pos1 = atomicAdd(&g_count[e1], 1);
        g_tok [e1 * T_TOK + pos1] = t;
        g_wt  [e1 * T_TOK + pos1] = w1;
        g_slot[e1 * T_TOK + pos1] = 1;
    }
}

// ======================= GEMM1: silu(x Wg^T) * (x Wu^T) =====================
// CTA: 128 tokens x 64 inter. kc=32, 3-stage cp.async. 8 warps: 0-3 gate, 4-7 up.
// stage (30720B): Ahi(10240) Alo(10240) Bg_hi(5120) Bu_hi(5120)
#define G1_STG   30720
#define G1_SMEM  (3 * G1_STG + 512)

__device__ __forceinline__ void g1_load(uint32_t sbase, int st, int kt,
                                        int e, int col0, const int* toks_s) {
    const int k0 = kt * 32;
    const uint32_t sb = sbase + st * G1_STG;
    const int tid = threadIdx.x;
#pragma unroll
    for (int j = 0; j < 2; j++) {
        int chunk = tid + j * 256;
        int row = chunk >> 2, c = chunk & 3;
        size_t go = (size_t)toks_s[row] * H_DIM + k0 + c * 8;
        cp16(sb + row * 80 + c * 16, cx_hi + go);
        cp16(sb + 10240 + row * 80 + c * 16, cx_lo + go);
    }
    {
        int row = tid >> 2, c = tid & 3;
        size_t go = ((size_t)(e * I_DIM + col0 + row)) * H_DIM + k0 + c * 8;
        cp16(sb + 20480 + row * 80 + c * 16, cwg_hi + go);
        cp16(sb + 25600 + row * 80 + c * 16, cwu_hi + go);
    }
}

__global__ __launch_bounds__(256, 2) void k_gemm1() {
    extern __shared__ char smem[];
    const int e    = blockIdx.z;
    const int n    = g_count[e];
    const int row0 = blockIdx.x * 128;
    if (row0 >= n) return;
    const int col0 = blockIdx.y * 64;
    const int tid  = threadIdx.x;
    const int l    = tid & 31;
    const int w    = tid >> 5;
    const bool isU = (w >= 4);
    const int m0   = (w & 3) * 32;

    int* toks_s = (int*)(smem + 3 * G1_STG);
    if (tid < 128) {
        int r = row0 + tid;
        toks_s[tid] = (r < n) ? g_tok[e * T_TOK + r] : 0;
    }
    __syncthreads();

    const uint32_t sbase = smem_u32(smem);

    float acc[2][8][4];
#pragma unroll
    for (int a = 0; a < 2; a++)
#pragma unroll
        for (int b = 0; b < 8; b++)
#pragma unroll
            for (int c = 0; c < 4; c++) acc[a][b][c] = 0.f;

    const int KT = H_DIM / 32;  // 64
    g1_load(sbase, 0, 0, e, col0, toks_s);
    CP_COMMIT();
    g1_load(sbase, 1, 1, e, col0, toks_s);
    CP_COMMIT();

    const uint32_t arow = (uint32_t)((l & 7) + ((l >> 3) & 1) * 8);
    const uint32_t brow = (uint32_t)((l & 7) + ((l >> 4) & 1) * 8);

    int st = 0;
    for (int kt = 0; kt < KT; kt++) {
        if (kt + 2 < KT) g1_load(sbase, (st + 2) % 3, kt + 2, e, col0, toks_s);
        CP_COMMIT();      // empty group near tail keeps wait-count invariant
        CP_WAIT(2);
        __syncthreads();

        const uint32_t sA  = sbase + st * G1_STG;
        const uint32_t sAl = sA + 10240;
        const uint32_t sB  = sA + (isU ? 25600 : 20480);

#pragma unroll
        for (int ks = 0; ks < 2; ks++) {
            const uint32_t acol = (uint32_t)(((l >> 4) * 8 + ks * 16) * 2);
            const uint32_t bcol = (uint32_t)((((l >> 3) & 1) * 8 + ks * 16) * 2);
            uint32_t ah[2][4], al[2][4];
            ldm4(ah[0][0], ah[0][1], ah[0][2], ah[0][3], sA  + (m0 + arow) * 80 + acol);
            ldm4(ah[1][0], ah[1][1], ah[1][2], ah[1][3], sA  + (m0 + 16 + arow) * 80 + acol);
            ldm4(al[0][0], al[0][1], al[0][2], al[0][3], sAl + (m0 + arow) * 80 + acol);
            ldm4(al[1][0], al[1][1], al[1][2], al[1][3], sAl + (m0 + 16 + arow) * 80 + acol);
#pragma unroll
            for (int np = 0; np < 4; np++) {
                uint32_t bh[4];
                ldm4(bh[0], bh[1], bh[2], bh[3], sB + (np * 16 + brow) * 80 + bcol);
#pragma unroll
                for (int mt = 0; mt < 2; mt++) {
                    mma16816(acc[mt][np * 2 + 0], ah[mt][0], ah[mt][1], ah[mt][2], ah[mt][3], bh[0], bh[1]);
                    mma16816(acc[mt][np * 2 + 1], ah[mt][0], ah[mt][1], ah[mt][2], ah[mt][3], bh[2], bh[3]);
                    mma16816(acc[mt][np * 2 + 0], al[mt][0], al[mt][1], al[mt][2], al[mt][3], bh[0], bh[1]);
                    mma16816(acc[mt][np * 2 + 1], al[mt][0], al[mt][1], al[mt][2], al[mt][3], bh[2], bh[3]);
                }
            }
        }
        __syncthreads();
        st = (st + 1) % 3;
    }

    // epilogue: U warps -> smem, G warps compute silu(g)*u, store fp16 hi
    float* Ub = (float*)smem;   // pitch 72 floats
    if (isU) {
#pragma unroll
        for (int mt = 0; mt < 2; mt++)
#pragma unroll
            for (int nt = 0; nt < 8; nt++) {
                int m  = m0 + mt * 16 + (l >> 2);
                int cc = nt * 8 + (l & 3) * 2;
                *(float2*)&Ub[m * 72 + cc]       = make_float2(acc[mt][nt][0], acc[mt][nt][1]);
                *(float2*)&Ub[(m + 8) * 72 + cc] = make_float2(acc[mt][nt][2], acc[mt][nt][3]);
            }
    }
    __syncthreads();
    if (!isU) {
#pragma unroll
        for (int mt = 0; mt < 2; mt++)
#pragma unroll
            for (int nt = 0; nt < 8; nt++) {
                int m  = m0 + mt * 16 + (l >> 2);
                int cc = nt * 8 + (l & 3) * 2;
#pragma unroll
                for (int half = 0; half < 2; half++) {
                    int mm = m + half * 8;
                    int rr = row0 + mm;
                    if (rr < n) {
                        float2 u = *(float2*)&Ub[mm * 72 + cc];
                        float g0 = acc[mt][nt][half * 2 + 0];
                        float g1 = acc[mt][nt][half * 2 + 1];
                        float a0 = g0 / (1.f + __expf(-g0)) * u.x;
                        float a1 = g1 / (1.f + __expf(-g1)) * u.y;
                        size_t idx = ((size_t)e * T_TOK + rr) * I_DIM + col0 + cc;
                        *(uint32_t*)(act_hi + idx) = pack2h(a0, a1);
                    }
                }
            }
    }
}

// ======================= GEMM2: out += rw * (act_hi Wd^T) ===================
// CTA: 128 rows x 128 H-cols. kc=32, 3-stage. 8 warps in 4x2 grid, warp 32x64.
// stage (20480B): Ahi(10240) B_hi(10240)
#define G2_STG   20480
#define G2_SMEM  (3 * G2_STG + 1536)

__device__ __forceinline__ void g2_load(uint32_t sbase, int st, int kt,
                                        int e, int row0, int col0) {
    const int k0 = kt * 32;
    const uint32_t sb = sbase + st * G2_STG;
    const int tid = threadIdx.x;
#pragma unroll
    for (int j = 0; j < 2; j++) {
        int chunk = tid + j * 256;
        int row = chunk >> 2, c = chunk & 3;
        size_t ga = ((size_t)e * T_TOK + row0 + row) * I_DIM + k0 + c * 8;
        cp16(sb + row * 80 + c * 16, act_hi + ga);
        size_t gb = ((size_t)(e * H_DIM + col0 + row)) * I_DIM + k0 + c * 8;
        cp16(sb + 10240 + row * 80 + c * 16, cwd_hi + gb);
    }
}

__global__ __launch_bounds__(256, 2) void k_gemm2(float* __restrict__ out) {
    extern __shared__ char smem[];
    const int e    = blockIdx.z;
    const int n    = g_count[e];
    const int row0 = blockIdx.x * 128;
    if (row0 >= n) return;
    const int col0 = blockIdx.y * 128;
    const int tid  = threadIdx.x;
    const int l    = tid & 31;
    const int w    = tid >> 5;
    const int m0   = (w & 3) * 32;
    const int nw0  = (w >> 2) * 64;

    int*   toks_s = (int*)  (smem + 3 * G2_STG);
    float* ws_s   = (float*)(smem + 3 * G2_STG + 512);
    if (tid < 128) {
        int r = row0 + tid;
        if (r < n) {
            toks_s[tid] = g_tok[e * T_TOK + r];
            ws_s[tid]   = g_wt [e * T_TOK + r];
        } else { toks_s[tid] = 0; ws_s[tid] = 0.f; }
    }
    __syncthreads();

    const uint32_t sbase = smem_u32(smem);

    float acc[2][8][4];
#pragma unroll
    for (int a = 0; a < 2; a++)
#pragma unroll
        for (int b = 0; b < 8; b++)
#pragma unroll
            for (int c = 0; c < 4; c++) acc[a][b][c] = 0.f;

    const int KT = I_DIM / 32;  // 32
    g2_load(sbase, 0, 0, e, row0, col0);
    CP_COMMIT();
    g2_load(sbase, 1, 1, e, row0, col0);
    CP_COMMIT();

    const uint32_t arow = (uint32_t)((l & 7) + ((l >> 3) & 1) * 8);
    const uint32_t brow = (uint32_t)((l & 7) + ((l >> 4) & 1) * 8);

    int st = 0;
    for (int kt = 0; kt < KT; kt++) {
        if (kt + 2 < KT) g2_load(sbase, (st + 2) % 3, kt + 2, e, row0, col0);
        CP_COMMIT();
        CP_WAIT(2);
        __syncthreads();

        const uint32_t sA = sbase + st * G2_STG;
        const uint32_t sB = sA + 10240;

#pragma unroll
        for (int ks = 0; ks < 2; ks++) {
            const uint32_t acol = (uint32_t)(((l >> 4) * 8 + ks * 16) * 2);
            const uint32_t bcol = (uint32_t)((((l >> 3) & 1) * 8 + ks * 16) * 2);
            uint32_t ah[2][4];
            ldm4(ah[0][0], ah[0][1], ah[0][2], ah[0][3], sA + (m0 + arow) * 80 + acol);
            ldm4(ah[1][0], ah[1][1], ah[1][2], ah[1][3], sA + (m0 + 16 + arow) * 80 + acol);
#pragma unroll
            for (int np = 0; np < 4; np++) {
                uint32_t bh[4];
                ldm4(bh[0], bh[1], bh[2], bh[3], sB + (nw0 + np * 16 + brow) * 80 + bcol);
#pragma unroll
                for (int mt = 0; mt < 2; mt++) {
                    mma16816(acc[mt][np * 2 + 0], ah[mt][0], ah[mt][1], ah[mt][2], ah[mt][3], bh[0], bh[1]);
                    mma16816(acc[mt][np * 2 + 1], ah[mt][0], ah[mt][1], ah[mt][2], ah[mt][3], bh[2], bh[3]);
                }
            }
        }
        __syncthreads();
        st = (st + 1) % 3;
    }

    // epilogue: scale by routing weight, atomic-add into out (2 addends/elem)
#pragma unroll
    for (int mt = 0; mt < 2; mt++)
#pragma unroll
        for (int nt = 0; nt < 8; nt++) {
            int m  = m0 + mt * 16 + (l >> 2);
            int cc = nw0 + nt * 8 + (l & 3) * 2;
#pragma unroll
            for (int half = 0; half < 2; half++) {
                int mm = m + half * 8;
                if (row0 + mm < n) {
                    int   t  = toks_s[mm];
                    float wt = ws_s[mm];
                    float* dst = out + (size_t)t * H_DIM + col0 + cc;
                    atomicAdd(dst + 0, acc[mt][nt][half * 2 + 0] * wt);
                    atomicAdd(dst + 1, acc[mt][nt][half * 2 + 1] * wt);
                }
            }
        }
}

// ---------------- launch -----------------------------------------------------
extern "C" void kernel_launch(void* const* d_in, const int* in_sizes, int n_in,
                              void* d_out, int out_size) {
    const float* x  = (const float*)d_in[0];
    const float* gw = (const float*)d_in[1];
    const float* wg = (const float*)d_in[2];
    const float* wu = (const float*)d_in[3];
    const float* wd = (const float*)d_in[4];
    float* out = (float*)d_out;

    static int attr_done = 0;
    if (!attr_done) {
        cudaFuncSetAttribute(k_gemm1, cudaFuncAttributeMaxDynamicSharedMemorySize, G1_SMEM);
        cudaFuncSetAttribute(k_gemm2, cudaFuncAttributeMaxDynamicSharedMemorySize, G2_SMEM);
        attr_done = 1;
    }

    // launch order chosen so k_gemm1 is launch #4 (ncu capture slot)
    k_init<<<1, 32>>>();
    k_router<<<(T_TOK * 32) / 256, 256>>>(x, gw);
    k_conv<<<(N4_X + 3 * N4_W + 255) / 256, 256>>>((const float4*)x, (const float4*)wg,
                                                   (const float4*)wu, (const float4*)wd);
    k_gemm1<<<dim3(T_TOK / 128, I_DIM / 64, N_EXP), 256, G1_SMEM>>>();
    k_zero<<<(T_TOK * H_DIM / 4 + 255) / 256, 256>>>((float4*)out);
    k_gemm2<<<dim3(T_TOK / 128, H_DIM / 128, N_EXP), 256, G2_SMEM>>>(out);
}

// round 6
// speedup vs baseline: 5.6561x; 1.3168x over previous
#include <cuda_runtime.h>
#include <cuda_fp16.h>
#include <math.h>
#include <stdint.h>

#define T_TOK 4096
#define H_DIM 2048
#define I_DIM 1024
#define N_EXP 8

// ---------------- scratch (static device globals; no allocation) ------------
__device__ int   g_count[N_EXP];
__device__ int   g_tok [N_EXP * T_TOK];
__device__ float g_wt  [N_EXP * T_TOK];
__device__ int   g_slot[N_EXP * T_TOK];
__device__ float g_part[(size_t)T_TOK * 2 * H_DIM];   // 64 MB

// converted fp16 operands (hi only, single-term fp16 GEMMs)
__device__ __half cx_hi [(size_t)T_TOK * H_DIM];
__device__ __half cwg_hi[(size_t)N_EXP * I_DIM * H_DIM];
__device__ __half cwu_hi[(size_t)N_EXP * I_DIM * H_DIM];
__device__ __half cwd_hi[(size_t)N_EXP * H_DIM * I_DIM];
__device__ __half act_hi[(size_t)N_EXP * T_TOK * I_DIM];

// ======================= helpers ============================================
__device__ __forceinline__ uint32_t smem_u32(const void* p) {
    uint32_t a;
    asm("{ .reg .u64 t; cvta.to.shared.u64 t, %1; cvt.u32.u64 %0, t; }"
        : "=r"(a) : "l"(p));
    return a;
}

__device__ __forceinline__ void cp16(uint32_t s, const void* g) {
    asm volatile("cp.async.cg.shared.global [%0], [%1], 16;"
                 :: "r"(s), "l"(g) : "memory");
}
#define CP_COMMIT() asm volatile("cp.async.commit_group;" ::: "memory")
#define CP_WAIT(n)  asm volatile("cp.async.wait_group %0;" :: "n"(n) : "memory")

__device__ __forceinline__ void ldm4(uint32_t& r0, uint32_t& r1,
                                     uint32_t& r2, uint32_t& r3, uint32_t a) {
    asm volatile("ldmatrix.sync.aligned.m8n8.x4.shared.b16 {%0,%1,%2,%3}, [%4];"
                 : "=r"(r0), "=r"(r1), "=r"(r2), "=r"(r3) : "r"(a));
}

__device__ __forceinline__ void mma16816(float* c, uint32_t a0, uint32_t a1,
                                         uint32_t a2, uint32_t a3,
                                         uint32_t b0, uint32_t b1) {
    asm volatile(
        "mma.sync.aligned.m16n8k16.row.col.f32.f16.f16.f32 "
        "{%0,%1,%2,%3}, {%4,%5,%6,%7}, {%8,%9}, {%0,%1,%2,%3};"
        : "+f"(c[0]), "+f"(c[1]), "+f"(c[2]), "+f"(c[3])
        : "r"(a0), "r"(a1), "r"(a2), "r"(a3), "r"(b0), "r"(b1));
}

__device__ __forceinline__ uint32_t pack2h(float a, float b) {
    __half2 hv = __floats2half2_rn(a, b);
    return *reinterpret_cast<uint32_t*>(&hv);
}

// ---------------- init ------------------------------------------------------
__global__ void k_init() {
    if (threadIdx.x < N_EXP) g_count[threadIdx.x] = 0;
}

// ---------------- conversion (single launch): all four tensors -> fp16 ------
#define N4_X (T_TOK * H_DIM / 4)                 // 2M float4
#define N4_W (N_EXP * I_DIM * H_DIM / 4)         // 4M float4 each
__global__ void k_conv(const float4* __restrict__ x,  const float4* __restrict__ wg,
                       const float4* __restrict__ wu, const float4* __restrict__ wd) {
    int i = blockIdx.x * 256 + threadIdx.x;
    const float4* src;
    uint2* dst;
    int j = i;
    if (i < N4_X)                      { src = x;  dst = (uint2*)cx_hi; }
    else if ((j -= N4_X) < N4_W)       { src = wg; dst = (uint2*)cwg_hi; }
    else if ((j -= N4_W) < N4_W)       { src = wu; dst = (uint2*)cwu_hi; }
    else if ((j -= N4_W) < N4_W)       { src = wd; dst = (uint2*)cwd_hi; }
    else return;
    float4 v = src[j];
    dst[j] = make_uint2(pack2h(v.x, v.y), pack2h(v.z, v.w));
}

// ---------------- router ----------------------------------------------------
__global__ void k_router(const float* __restrict__ x,
                         const float* __restrict__ gw) {
    int gid  = blockIdx.x * blockDim.x + threadIdx.x;
    int t    = gid >> 5;
    int lane = gid & 31;
    if (t >= T_TOK) return;

    const float* xr = x + (size_t)t * H_DIM;
    float acc[N_EXP];
#pragma unroll
    for (int e = 0; e < N_EXP; e++) acc[e] = 0.f;

    for (int h = lane; h < H_DIM; h += 32) {
        float xv = xr[h];
#pragma unroll
        for (int e = 0; e < N_EXP; e++) acc[e] += xv * gw[e * H_DIM + h];
    }
#pragma unroll
    for (int e = 0; e < N_EXP; e++) {
#pragma unroll
        for (int o = 16; o > 0; o >>= 1)
            acc[e] += __shfl_xor_sync(0xffffffffu, acc[e], o);
    }

    if (lane == 0) {
        float m = acc[0];
#pragma unroll
        for (int e = 1; e < N_EXP; e++) m = fmaxf(m, acc[e]);
        float p[N_EXP];
        float s = 0.f;
#pragma unroll
        for (int e = 0; e < N_EXP; e++) { p[e] = expf(acc[e] - m); s += p[e]; }
        float inv = 1.f / s;
#pragma unroll
        for (int e = 0; e < N_EXP; e++) p[e] *= inv;

        int e0 = 0;
#pragma unroll
        for (int e = 1; e < N_EXP; e++) if (p[e] > p[e0]) e0 = e;
        int e1 = -1;
#pragma unroll
        for (int e = 0; e < N_EXP; e++) {
            if (e == e0) continue;
            if (e1 < 0 || p[e] > p[e1]) e1 = e;
        }
        float den = p[e0] + p[e1];
        float w0 = p[e0] / den;
        float w1 = p[e1] / den;

        int pos0 = atomicAdd(&g_count[e0], 1);
        g_tok [e0 * T_TOK + pos0] = t;
        g_wt  [e0 * T_TOK + pos0] = w0;
        g_slot[e0 * T_TOK + pos0] = 0;

        int pos1 = atomicAdd(&g_count[e1], 1);
        g_tok [e1 * T_TOK + pos1] = t;
        g_wt  [e1 * T_TOK + pos1] = w1;
        g_slot[e1 * T_TOK + pos1] = 1;
    }
}

// ======================= GEMM1: silu(x Wg^T) * (x Wu^T) =====================
// CTA: 128 tokens x 64 inter. kc=32, 3-stage cp.async. 8 warps: 0-3 gate, 4-7 up.
// stage (20480B): A(10240) Bg(5120) Bu(5120)
#define G1_STG   20480
#define G1_SMEM  (3 * G1_STG + 512)

__device__ __forceinline__ void g1_load(uint32_t sbase, int st, int kt,
                                        int e, int col0, const int* toks_s) {
    const int k0 = kt * 32;
    const uint32_t sb = sbase + st * G1_STG;
    const int tid = threadIdx.x;
#pragma unroll
    for (int j = 0; j < 2; j++) {
        int chunk = tid + j * 256;
        int row = chunk >> 2, c = chunk & 3;
        size_t go = (size_t)toks_s[row] * H_DIM + k0 + c * 8;
        cp16(sb + row * 80 + c * 16, cx_hi + go);
    }
    {
        int row = tid >> 2, c = tid & 3;
        size_t go = ((size_t)(e * I_DIM + col0 + row)) * H_DIM + k0 + c * 8;
        cp16(sb + 10240 + row * 80 + c * 16, cwg_hi + go);
        cp16(sb + 15360 + row * 80 + c * 16, cwu_hi + go);
    }
}

__global__ __launch_bounds__(256, 2) void k_gemm1() {
    extern __shared__ char smem[];
    const int e    = blockIdx.z;
    const int n    = g_count[e];
    const int row0 = blockIdx.x * 128;
    if (row0 >= n) return;
    const int col0 = blockIdx.y * 64;
    const int tid  = threadIdx.x;
    const int l    = tid & 31;
    const int w    = tid >> 5;
    const bool isU = (w >= 4);
    const int m0   = (w & 3) * 32;

    int* toks_s = (int*)(smem + 3 * G1_STG);
    if (tid < 128) {
        int r = row0 + tid;
        toks_s[tid] = (r < n) ? g_tok[e * T_TOK + r] : 0;
    }
    __syncthreads();

    const uint32_t sbase = smem_u32(smem);

    float acc[2][8][4];
#pragma unroll
    for (int a = 0; a < 2; a++)
#pragma unroll
        for (int b = 0; b < 8; b++)
#pragma unroll
            for (int c = 0; c < 4; c++) acc[a][b][c] = 0.f;

    const int KT = H_DIM / 32;  // 64
    g1_load(sbase, 0, 0, e, col0, toks_s);
    CP_COMMIT();
    g1_load(sbase, 1, 1, e, col0, toks_s);
    CP_COMMIT();

    const uint32_t arow = (uint32_t)((l & 7) + ((l >> 3) & 1) * 8);
    const uint32_t brow = (uint32_t)((l & 7) + ((l >> 4) & 1) * 8);

    int st = 0;
    for (int kt = 0; kt < KT; kt++) {
        if (kt + 2 < KT) g1_load(sbase, (st + 2) % 3, kt + 2, e, col0, toks_s);
        CP_COMMIT();      // empty group near tail keeps wait-count invariant
        CP_WAIT(2);
        __syncthreads();

        const uint32_t sA = sbase + st * G1_STG;
        const uint32_t sB = sA + (isU ? 15360 : 10240);

#pragma unroll
        for (int ks = 0; ks < 2; ks++) {
            const uint32_t acol = (uint32_t)(((l >> 4) * 8 + ks * 16) * 2);
            const uint32_t bcol = (uint32_t)((((l >> 3) & 1) * 8 + ks * 16) * 2);
            uint32_t ah[2][4];
            ldm4(ah[0][0], ah[0][1], ah[0][2], ah[0][3], sA + (m0 + arow) * 80 + acol);
            ldm4(ah[1][0], ah[1][1], ah[1][2], ah[1][3], sA + (m0 + 16 + arow) * 80 + acol);
#pragma unroll
            for (int np = 0; np < 4; np++) {
                uint32_t bh[4];
                ldm4(bh[0], bh[1], bh[2], bh[3], sB + (np * 16 + brow) * 80 + bcol);
#pragma unroll
                for (int mt = 0; mt < 2; mt++) {
                    mma16816(acc[mt][np * 2 + 0], ah[mt][0], ah[mt][1], ah[mt][2], ah[mt][3], bh[0], bh[1]);
                    mma16816(acc[mt][np * 2 + 1], ah[mt][0], ah[mt][1], ah[mt][2], ah[mt][3], bh[2], bh[3]);
                }
            }
        }
        __syncthreads();
        st = (st + 1) % 3;
    }

    // epilogue: U warps -> smem, G warps compute silu(g)*u, store fp16
    float* Ub = (float*)smem;   // pitch 72 floats (36KB < stage area)
    if (isU) {
#pragma unroll
        for (int mt = 0; mt < 2; mt++)
#pragma unroll
            for (int nt = 0; nt < 8; nt++) {
                int m  = m0 + mt * 16 + (l >> 2);
                int cc = nt * 8 + (l & 3) * 2;
                *(float2*)&Ub[m * 72 + cc]       = make_float2(acc[mt][nt][0], acc[mt][nt][1]);
                *(float2*)&Ub[(m + 8) * 72 + cc] = make_float2(acc[mt][nt][2], acc[mt][nt][3]);
            }
    }
    __syncthreads();
    if (!isU) {
#pragma unroll
        for (int mt = 0; mt < 2; mt++)
#pragma unroll
            for (int nt = 0; nt < 8; nt++) {
                int m  = m0 + mt * 16 + (l >> 2);
                int cc = nt * 8 + (l & 3) * 2;
#pragma unroll
                for (int half = 0; half < 2; half++) {
                    int mm = m + half * 8;
                    int rr = row0 + mm;
                    if (rr < n) {
                        float2 u = *(float2*)&Ub[mm * 72 + cc];
                        float g0 = acc[mt][nt][half * 2 + 0];
                        float g1 = acc[mt][nt][half * 2 + 1];
                        float a0 = g0 / (1.f + __expf(-g0)) * u.x;
                        float a1 = g1 / (1.f + __expf(-g1)) * u.y;
                        size_t idx = ((size_t)e * T_TOK + rr) * I_DIM + col0 + cc;
                        *(uint32_t*)(act_hi + idx) = pack2h(a0, a1);
                    }
                }
            }
    }
}

// ======================= GEMM2: part = rw * (act Wd^T) ======================
// CTA: 128 rows x 128 H-cols. kc=32, 3-stage. 8 warps in 4x2 grid, warp 32x64.
// stage (20480B): A(10240) B(10240). Plain stores to g_part (no atomics).
#define G2_STG   20480
#define G2_SMEM  (3 * G2_STG + 2048)

__device__ __forceinline__ void g2_load(uint32_t sbase, int st, int kt,
                                        int e, int row0, int col0) {
    const int k0 = kt * 32;
    const uint32_t sb = sbase + st * G2_STG;
    const int tid = threadIdx.x;
#pragma unroll
    for (int j = 0; j < 2; j++) {
        int chunk = tid + j * 256;
        int row = chunk >> 2, c = chunk & 3;
        size_t ga = ((size_t)e * T_TOK + row0 + row) * I_DIM + k0 + c * 8;
        cp16(sb + row * 80 + c * 16, act_hi + ga);
        size_t gb = ((size_t)(e * H_DIM + col0 + row)) * I_DIM + k0 + c * 8;
        cp16(sb + 10240 + row * 80 + c * 16, cwd_hi + gb);
    }
}

__global__ __launch_bounds__(256, 2) void k_gemm2() {
    extern __shared__ char smem[];
    const int e    = blockIdx.z;
    const int n    = g_count[e];
    const int row0 = blockIdx.x * 128;
    if (row0 >= n) return;
    const int col0 = blockIdx.y * 128;
    const int tid  = threadIdx.x;
    const int l    = tid & 31;
    const int w    = tid >> 5;
    const int m0   = (w & 3) * 32;
    const int nw0  = (w >> 2) * 64;

    int*   toks_s = (int*)  (smem + 3 * G2_STG);
    float* ws_s   = (float*)(smem + 3 * G2_STG + 512);
    int*   ks_s   = (int*)  (smem + 3 * G2_STG + 1024);
    if (tid < 128) {
        int r = row0 + tid;
        if (r < n) {
            toks_s[tid] = g_tok [e * T_TOK + r];
            ws_s[tid]   = g_wt  [e * T_TOK + r];
            ks_s[tid]   = g_slot[e * T_TOK + r];
        } else { toks_s[tid] = 0; ws_s[tid] = 0.f; ks_s[tid] = 0; }
    }
    __syncthreads();

    const uint32_t sbase = smem_u32(smem);

    float acc[2][8][4];
#pragma unroll
    for (int a = 0; a < 2; a++)
#pragma unroll
        for (int b = 0; b < 8; b++)
#pragma unroll
            for (int c = 0; c < 4; c++) acc[a][b][c] = 0.f;

    const int KT = I_DIM / 32;  // 32
    g2_load(sbase, 0, 0, e, row0, col0);
    CP_COMMIT();
    g2_load(sbase, 1, 1, e, row0, col0);
    CP_COMMIT();

    const uint32_t arow = (uint32_t)((l & 7) + ((l >> 3) & 1) * 8);
    const uint32_t brow = (uint32_t)((l & 7) + ((l >> 4) & 1) * 8);

    int st = 0;
    for (int kt = 0; kt < KT; kt++) {
        if (kt + 2 < KT) g2_load(sbase, (st + 2) % 3, kt + 2, e, row0, col0);
        CP_COMMIT();
        CP_WAIT(2);
        __syncthreads();

        const uint32_t sA = sbase + st * G2_STG;
        const uint32_t sB = sA + 10240;

#pragma unroll
        for (int ks = 0; ks < 2; ks++) {
            const uint32_t acol = (uint32_t)(((l >> 4) * 8 + ks * 16) * 2);
            const uint32_t bcol = (uint32_t)((((l >> 3) & 1) * 8 + ks * 16) * 2);
            uint32_t ah[2][4];
            ldm4(ah[0][0], ah[0][1], ah[0][2], ah[0][3], sA + (m0 + arow) * 80 + acol);
            ldm4(ah[1][0], ah[1][1], ah[1][2], ah[1][3], sA + (m0 + 16 + arow) * 80 + acol);
#pragma unroll
            for (int np = 0; np < 4; np++) {
                uint32_t bh[4];
                ldm4(bh[0], bh[1], bh[2], bh[3], sB + (nw0 + np * 16 + brow) * 80 + bcol);
#pragma unroll
                for (int mt = 0; mt < 2; mt++) {
                    mma16816(acc[mt][np * 2 + 0], ah[mt][0], ah[mt][1], ah[mt][2], ah[mt][3], bh[0], bh[1]);
                    mma16816(acc[mt][np * 2 + 1], ah[mt][0], ah[mt][1], ah[mt][2], ah[mt][3], bh[2], bh[3]);
                }
            }
        }
        __syncthreads();
        st = (st + 1) % 3;
    }

    // epilogue: scale by routing weight, plain float2 stores into g_part
#pragma unroll
    for (int mt = 0; mt < 2; mt++)
#pragma unroll
        for (int nt = 0; nt < 8; nt++) {
            int m  = m0 + mt * 16 + (l >> 2);
            int cc = nw0 + nt * 8 + (l & 3) * 2;
#pragma unroll
            for (int half = 0; half < 2; half++) {
                int mm = m + half * 8;
                if (row0 + mm < n) {
                    int   t  = toks_s[mm];
                    int   k  = ks_s[mm];
                    float wt = ws_s[mm];
                    float2 v = make_float2(acc[mt][nt][half * 2 + 0] * wt,
                                           acc[mt][nt][half * 2 + 1] * wt);
                    *(float2*)&g_part[((size_t)t * 2 + k) * H_DIM + col0 + cc] = v;
                }
            }
        }
}

// ---------------- combine ----------------------------------------------------
__global__ void k_combine(float* __restrict__ out) {
    int i = blockIdx.x * 256 + threadIdx.x;
    if (i >= T_TOK * H_DIM) return;
    int t = i >> 11;
    int h = i & (H_DIM - 1);
    out[i] = g_part[((size_t)t * 2 + 0) * H_DIM + h] +
             g_part[((size_t)t * 2 + 1) * H_DIM + h];
}

// ---------------- launch -----------------------------------------------------
extern "C" void kernel_launch(void* const* d_in, const int* in_sizes, int n_in,
                              void* d_out, int out_size) {
    const float* x  = (const float*)d_in[0];
    const float* gw = (const float*)d_in[1];
    const float* wg = (const float*)d_in[2];
    const float* wu = (const float*)d_in[3];
    const float* wd = (const float*)d_in[4];
    float* out = (float*)d_out;

    static int attr_done = 0;
    if (!attr_done) {
        cudaFuncSetAttribute(k_gemm1, cudaFuncAttributeMaxDynamicSharedMemorySize, G1_SMEM);
        cudaFuncSetAttribute(k_gemm2, cudaFuncAttributeMaxDynamicSharedMemorySize, G2_SMEM);
        attr_done = 1;
    }

    // launch order keeps k_gemm1 at ncu's capture slot (#4)
    k_init<<<1, 32>>>();
    k_router<<<(T_TOK * 32) / 256, 256>>>(x, gw);
    k_conv<<<(N4_X + 3 * N4_W + 255) / 256, 256>>>((const float4*)x, (const float4*)wg,
                                                   (const float4*)wu, (const float4*)wd);
    k_gemm1<<<dim3(T_TOK / 128, I_DIM / 64, N_EXP), 256, G1_SMEM>>>();
    k_gemm2<<<dim3(T_TOK / 128, H_DIM / 128, N_EXP), 256, G2_SMEM>>>();
    k_combine<<<(T_TOK * H_DIM + 255) / 256, 256>>>(out);
}

// round 7
// speedup vs baseline: 6.0110x; 1.0627x over previous
#include <cuda_runtime.h>
#include <cuda_fp16.h>
#include <math.h>
#include <stdint.h>

#define T_TOK 4096
#define H_DIM 2048
#define I_DIM 1024
#define N_EXP 8

// ---------------- scratch (static device globals; no allocation) ------------
__device__ int   g_count[N_EXP];
__device__ int   g_tok [N_EXP * T_TOK];
__device__ float g_wt  [N_EXP * T_TOK];
__device__ int   g_slot[N_EXP * T_TOK];
__device__ float g_part[(size_t)T_TOK * 2 * H_DIM];   // 64 MB

// converted fp16 operands
__device__ __half cx_hi [(size_t)T_TOK * H_DIM];
__device__ __half cwg_hi[(size_t)N_EXP * I_DIM * H_DIM];
__device__ __half cwu_hi[(size_t)N_EXP * I_DIM * H_DIM];
__device__ __half cwd_hi[(size_t)N_EXP * H_DIM * I_DIM];
__device__ __half act_hi[(size_t)N_EXP * T_TOK * I_DIM];

// ======================= helpers ============================================
__device__ __forceinline__ uint32_t smem_u32(const void* p) {
    uint32_t a;
    asm("{ .reg .u64 t; cvta.to.shared.u64 t, %1; cvt.u32.u64 %0, t; }"
        : "=r"(a) : "l"(p));
    return a;
}

__device__ __forceinline__ void cp16(uint32_t s, const void* g) {
    asm volatile("cp.async.cg.shared.global [%0], [%1], 16;"
                 :: "r"(s), "l"(g) : "memory");
}
#define CP_COMMIT() asm volatile("cp.async.commit_group;" ::: "memory")
#define CP_WAIT(n)  asm volatile("cp.async.wait_group %0;" :: "n"(n) : "memory")

__device__ __forceinline__ void ldm4(uint32_t& r0, uint32_t& r1,
                                     uint32_t& r2, uint32_t& r3, uint32_t a) {
    asm volatile("ldmatrix.sync.aligned.m8n8.x4.shared.b16 {%0,%1,%2,%3}, [%4];"
                 : "=r"(r0), "=r"(r1), "=r"(r2), "=r"(r3) : "r"(a));
}

__device__ __forceinline__ void mma16816(float* c, const uint32_t* a,
                                         uint32_t b0, uint32_t b1) {
    asm volatile(
        "mma.sync.aligned.m16n8k16.row.col.f32.f16.f16.f32 "
        "{%0,%1,%2,%3}, {%4,%5,%6,%7}, {%8,%9}, {%0,%1,%2,%3};"
        : "+f"(c[0]), "+f"(c[1]), "+f"(c[2]), "+f"(c[3])
        : "r"(a[0]), "r"(a[1]), "r"(a[2]), "r"(a[3]), "r"(b0), "r"(b1));
}

__device__ __forceinline__ uint32_t pack2h(float a, float b) {
    __half2 hv = __floats2half2_rn(a, b);
    return *reinterpret_cast<uint32_t*>(&hv);
}

// ---------------- init ------------------------------------------------------
__global__ void k_init() {
    if (threadIdx.x < N_EXP) g_count[threadIdx.x] = 0;
}

// ---------------- conversion (single launch) --------------------------------
#define N4_X (T_TOK * H_DIM / 4)
#define N4_W (N_EXP * I_DIM * H_DIM / 4)
__global__ void k_conv(const float4* __restrict__ x,  const float4* __restrict__ wg,
                       const float4* __restrict__ wu, const float4* __restrict__ wd) {
    int i = blockIdx.x * 256 + threadIdx.x;
    const float4* src;
    uint2* dst;
    int j = i;
    if (i < N4_X)                { src = x;  dst = (uint2*)cx_hi; }
    else if ((j -= N4_X) < N4_W) { src = wg; dst = (uint2*)cwg_hi; }
    else if ((j -= N4_W) < N4_W) { src = wu; dst = (uint2*)cwu_hi; }
    else if ((j -= N4_W) < N4_W) { src = wd; dst = (uint2*)cwd_hi; }
    else return;
    float4 v = src[j];
    dst[j] = make_uint2(pack2h(v.x, v.y), pack2h(v.z, v.w));
}

// ---------------- router ----------------------------------------------------
__global__ void k_router(const float* __restrict__ x,
                         const float* __restrict__ gw) {
    int gid  = blockIdx.x * blockDim.x + threadIdx.x;
    int t    = gid >> 5;
    int lane = gid & 31;
    if (t >= T_TOK) return;

    const float* xr = x + (size_t)t * H_DIM;
    float acc[N_EXP];
#pragma unroll
    for (int e = 0; e < N_EXP; e++) acc[e] = 0.f;

    for (int h = lane; h < H_DIM; h += 32) {
        float xv = xr[h];
#pragma unroll
        for (int e = 0; e < N_EXP; e++) acc[e] += xv * gw[e * H_DIM + h];
    }
#pragma unroll
    for (int e = 0; e < N_EXP; e++) {
#pragma unroll
        for (int o = 16; o > 0; o >>= 1)
            acc[e] += __shfl_xor_sync(0xffffffffu, acc[e], o);
    }

    if (lane == 0) {
        float m = acc[0];
#pragma unroll
        for (int e = 1; e < N_EXP; e++) m = fmaxf(m, acc[e]);
        float p[N_EXP];
        float s = 0.f;
#pragma unroll
        for (int e = 0; e < N_EXP; e++) { p[e] = expf(acc[e] - m); s += p[e]; }
        float inv = 1.f / s;
#pragma unroll
        for (int e = 0; e < N_EXP; e++) p[e] *= inv;

        int e0 = 0;
#pragma unroll
        for (int e = 1; e < N_EXP; e++) if (p[e] > p[e0]) e0 = e;
        int e1 = -1;
#pragma unroll
        for (int e = 0; e < N_EXP; e++) {
            if (e == e0) continue;
            if (e1 < 0 || p[e] > p[e1]) e1 = e;
        }
        float den = p[e0] + p[e1];
        float w0 = p[e0] / den;
        float w1 = p[e1] / den;

        int pos0 = atomicAdd(&g_count[e0], 1);
        g_tok [e0 * T_TOK + pos0] = t;
        g_wt  [e0 * T_TOK + pos0] = w0;
        g_slot[e0 * T_TOK + pos0] = 0;

        int pos1 = atomicAdd(&g_count[e1], 1);
        g_tok [e1 * T_TOK + pos1] = t;
        g_wt  [e1 * T_TOK + pos1] = w1;
        g_slot[e1 * T_TOK + pos1] = 1;
    }
}

// ======================= GEMM1: silu(x Wg^T) * (x Wu^T) =====================
// CTA: 128 threads (4 warps, 2x2), tile 128 tokens x 64 inter (gate+up).
// Warp tile 64x64. kc=32, 3-stage cp.async.
// stage (20480B): A(10240) Bg(5120) Bu(5120)
#define G1_STG   20480
#define G1_SMEM  (3 * G1_STG + 512)

__device__ __forceinline__ void g1_load(uint32_t sbase, int st, int kt,
                                        int e, int col0, const int* toks_s) {
    const int k0 = kt * 32;
    const uint32_t sb = sbase + st * G1_STG;
    const int tid = threadIdx.x;
#pragma unroll
    for (int j = 0; j < 4; j++) {             // A: 128 rows x 4 chunks
        int chunk = tid + j * 128;
        int row = chunk >> 2, c = chunk & 3;
        size_t go = (size_t)toks_s[row] * H_DIM + k0 + c * 8;
        cp16(sb + row * 80 + c * 16, cx_hi + go);
    }
#pragma unroll
    for (int j = 0; j < 2; j++) {             // Bg/Bu: 64 rows x 4 chunks each
        int chunk = tid + j * 128;
        int row = chunk >> 2, c = chunk & 3;
        size_t go = ((size_t)(e * I_DIM + col0 + row)) * H_DIM + k0 + c * 8;
        cp16(sb + 10240 + row * 80 + c * 16, cwg_hi + go);
        cp16(sb + 15360 + row * 80 + c * 16, cwu_hi + go);
    }
}

__global__ __launch_bounds__(128, 2) void k_gemm1() {
    extern __shared__ char smem[];
    const int e    = blockIdx.z;
    const int n    = g_count[e];
    const int row0 = blockIdx.x * 128;
    if (row0 >= n) return;
    const int col0 = blockIdx.y * 64;
    const int tid  = threadIdx.x;
    const int l    = tid & 31;
    const int w    = tid >> 5;
    const int m0   = (w & 1) * 64;
    const bool isU = (w >> 1);                // warps 2,3 = up

    int* toks_s = (int*)(smem + 3 * G1_STG);
    if (tid < 128) {
        int r = row0 + tid;
        toks_s[tid] = (r < n) ? g_tok[e * T_TOK + r] : 0;
    }
    __syncthreads();

    const uint32_t sbase = smem_u32(smem);

    float acc[4][8][4];
#pragma unroll
    for (int a = 0; a < 4; a++)
#pragma unroll
        for (int b = 0; b < 8; b++)
#pragma unroll
            for (int c = 0; c < 4; c++) acc[a][b][c] = 0.f;

    const int KT = H_DIM / 32;  // 64
    g1_load(sbase, 0, 0, e, col0, toks_s);
    CP_COMMIT();
    g1_load(sbase, 1, 1, e, col0, toks_s);
    CP_COMMIT();

    const uint32_t arow = (uint32_t)((l & 7) + ((l >> 3) & 1) * 8);
    const uint32_t brow = (uint32_t)((l & 7) + ((l >> 4) & 1) * 8);

    int st = 0;
    for (int kt = 0; kt < KT; kt++) {
        if (kt + 2 < KT) g1_load(sbase, (st + 2) % 3, kt + 2, e, col0, toks_s);
        CP_COMMIT();
        CP_WAIT(2);
        __syncthreads();

        const uint32_t sA = sbase + st * G1_STG;
        const uint32_t sB = sA + (isU ? 15360 : 10240);

#pragma unroll
        for (int ks = 0; ks < 2; ks++) {
            const uint32_t acol = (uint32_t)(((l >> 4) * 8 + ks * 16) * 2);
            const uint32_t bcol = (uint32_t)((((l >> 3) & 1) * 8 + ks * 16) * 2);
            uint32_t ah[4][4];
#pragma unroll
            for (int mt = 0; mt < 4; mt++)
                ldm4(ah[mt][0], ah[mt][1], ah[mt][2], ah[mt][3],
                     sA + (m0 + mt * 16 + arow) * 80 + acol);
#pragma unroll
            for (int np = 0; np < 4; np++) {
                uint32_t bh[4];
                ldm4(bh[0], bh[1], bh[2], bh[3], sB + (np * 16 + brow) * 80 + bcol);
#pragma unroll
                for (int mt = 0; mt < 4; mt++) {
                    mma16816(acc[mt][np * 2 + 0], ah[mt], bh[0], bh[1]);
                    mma16816(acc[mt][np * 2 + 1], ah[mt], bh[2], bh[3]);
                }
            }
        }
        __syncthreads();
        st = (st + 1) % 3;
    }

    // epilogue: up warps (2,3) -> smem, gate warps (0,1) compute silu(g)*u
    float* Ub = (float*)smem;   // 128 x 72 floats = 36864B (stages consumed)
    if (isU) {
#pragma unroll
        for (int mt = 0; mt < 4; mt++)
#pragma unroll
            for (int nt = 0; nt < 8; nt++) {
                int m  = m0 + mt * 16 + (l >> 2);
                int cc = nt * 8 + (l & 3) * 2;
                *(float2*)&Ub[m * 72 + cc]       = make_float2(acc[mt][nt][0], acc[mt][nt][1]);
                *(float2*)&Ub[(m + 8) * 72 + cc] = make_float2(acc[mt][nt][2], acc[mt][nt][3]);
            }
    }
    __syncthreads();
    if (!isU) {
#pragma unroll
        for (int mt = 0; mt < 4; mt++)
#pragma unroll
            for (int nt = 0; nt < 8; nt++) {
                int m  = m0 + mt * 16 + (l >> 2);
                int cc = nt * 8 + (l & 3) * 2;
#pragma unroll
                for (int half = 0; half < 2; half++) {
                    int mm = m + half * 8;
                    int rr = row0 + mm;
                    if (rr < n) {
                        float2 u = *(float2*)&Ub[mm * 72 + cc];
                        float g0 = acc[mt][nt][half * 2 + 0];
                        float g1 = acc[mt][nt][half * 2 + 1];
                        float a0 = g0 / (1.f + __expf(-g0)) * u.x;
                        float a1 = g1 / (1.f + __expf(-g1)) * u.y;
                        size_t idx = ((size_t)e * T_TOK + rr) * I_DIM + col0 + cc;
                        *(uint32_t*)(act_hi + idx) = pack2h(a0, a1);
                    }
                }
            }
    }
}

// ======================= GEMM2: part = rw * (act Wd^T) ======================
// CTA: 128 threads (4 warps, 2x2), tile 128 rows x 128 H-cols. Warp 64x64.
// stage (20480B): A(10240) B(10240)
#define G2_STG   20480
#define G2_SMEM  (3 * G2_STG + 2048)

__device__ __forceinline__ void g2_load(uint32_t sbase, int st, int kt,
                                        int e, int row0, int col0) {
    const int k0 = kt * 32;
    const uint32_t sb = sbase + st * G2_STG;
    const int tid = threadIdx.x;
#pragma unroll
    for (int j = 0; j < 4; j++) {
        int chunk = tid + j * 128;
        int row = chunk >> 2, c = chunk & 3;
        size_t ga = ((size_t)e * T_TOK + row0 + row) * I_DIM + k0 + c * 8;
        cp16(sb + row * 80 + c * 16, act_hi + ga);
        size_t gb = ((size_t)(e * H_DIM + col0 + row)) * I_DIM + k0 + c * 8;
        cp16(sb + 10240 + row * 80 + c * 16, cwd_hi + gb);
    }
}

__global__ __launch_bounds__(128, 2) void k_gemm2() {
    extern __shared__ char smem[];
    const int e    = blockIdx.z;
    const int n    = g_count[e];
    const int row0 = blockIdx.x * 128;
    if (row0 >= n) return;
    const int col0 = blockIdx.y * 128;
    const int tid  = threadIdx.x;
    const int l    = tid & 31;
    const int w    = tid >> 5;
    const int m0   = (w & 1) * 64;
    const int nw0  = (w >> 1) * 64;

    int*   toks_s = (int*)  (smem + 3 * G2_STG);
    float* ws_s   = (float*)(smem + 3 * G2_STG + 512);
    int*   ks_s   = (int*)  (smem + 3 * G2_STG + 1024);
    if (tid < 128) {
        int r = row0 + tid;
        if (r < n) {
            toks_s[tid] = g_tok [e * T_TOK + r];
            ws_s[tid]   = g_wt  [e * T_TOK + r];
            ks_s[tid]   = g_slot[e * T_TOK + r];
        } else { toks_s[tid] = 0; ws_s[tid] = 0.f; ks_s[tid] = 0; }
    }
    __syncthreads();

    const uint32_t sbase = smem_u32(smem);

    float acc[4][8][4];
#pragma unroll
    for (int a = 0; a < 4; a++)
#pragma unroll
        for (int b = 0; b < 8; b++)
#pragma unroll
            for (int c = 0; c < 4; c++) acc[a][b][c] = 0.f;

    const int KT = I_DIM / 32;  // 32
    g2_load(sbase, 0, 0, e, row0, col0);
    CP_COMMIT();
    g2_load(sbase, 1, 1, e, row0, col0);
    CP_COMMIT();

    const uint32_t arow = (uint32_t)((l & 7) + ((l >> 3) & 1) * 8);
    const uint32_t brow = (uint32_t)((l & 7) + ((l >> 4) & 1) * 8);

    int st = 0;
    for (int kt = 0; kt < KT; kt++) {
        if (kt + 2 < KT) g2_load(sbase, (st + 2) % 3, kt + 2, e, row0, col0);
        CP_COMMIT();
        CP_WAIT(2);
        __syncthreads();

        const uint32_t sA = sbase + st * G2_STG;
        const uint32_t sB = sA + 10240;

#pragma unroll
        for (int ks = 0; ks < 2; ks++) {
            const uint32_t acol = (uint32_t)(((l >> 4) * 8 + ks * 16) * 2);
            const uint32_t bcol = (uint32_t)((((l >> 3) & 1) * 8 + ks * 16) * 2);
            uint32_t ah[4][4];
#pragma unroll
            for (int mt = 0; mt < 4; mt++)
                ldm4(ah[mt][0], ah[mt][1], ah[mt][2], ah[mt][3],
                     sA + (m0 + mt * 16 + arow) * 80 + acol);
#pragma unroll
            for (int np = 0; np < 4; np++) {
                uint32_t bh[4];
                ldm4(bh[0], bh[1], bh[2], bh[3], sB + (nw0 + np * 16 + brow) * 80 + bcol);
#pragma unroll
                for (int mt = 0; mt < 4; mt++) {
                    mma16816(acc[mt][np * 2 + 0], ah[mt], bh[0], bh[1]);
                    mma16816(acc[mt][np * 2 + 1], ah[mt], bh[2], bh[3]);
                }
            }
        }
        __syncthreads();
        st = (st + 1) % 3;
    }

    // epilogue: scale by routing weight, plain float2 stores into g_part
#pragma unroll
    for (int mt = 0; mt < 4; mt++)
#pragma unroll
        for (int nt = 0; nt < 8; nt++) {
            int m  = m0 + mt * 16 + (l >> 2);
            int cc = nw0 + nt * 8 + (l & 3) * 2;
#pragma unroll
            for (int half = 0; half < 2; half++) {
                int mm = m + half * 8;
                if (row0 + mm < n) {
                    int   t  = toks_s[mm];
                    int   k  = ks_s[mm];
                    float wt = ws_s[mm];
                    float2 v = make_float2(acc[mt][nt][half * 2 + 0] * wt,
                                           acc[mt][nt][half * 2 + 1] * wt);
                    *(float2*)&g_part[((size_t)t * 2 + k) * H_DIM + col0 + cc] = v;
                }
            }
        }
}

// ---------------- combine ----------------------------------------------------
__global__ void k_combine(float* __restrict__ out) {
    int i = blockIdx.x * 256 + threadIdx.x;
    if (i >= T_TOK * H_DIM) return;
    int t = i >> 11;
    int h = i & (H_DIM - 1);
    out[i] = g_part[((size_t)t * 2 + 0) * H_DIM + h] +
             g_part[((size_t)t * 2 + 1) * H_DIM + h];
}

// ---------------- launch -----------------------------------------------------
extern "C" void kernel_launch(void* const* d_in, const int* in_sizes, int n_in,
                              void* d_out, int out_size) {
    const float* x  = (const float*)d_in[0];
    const float* gw = (const float*)d_in[1];
    const float* wg = (const float*)d_in[2];
    const float* wu = (const float*)d_in[3];
    const float* wd = (const float*)d_in[4];
    float* out = (float*)d_out;

    static int attr_done = 0;
    if (!attr_done) {
        cudaFuncSetAttribute(k_gemm1, cudaFuncAttributeMaxDynamicSharedMemorySize, G1_SMEM);
        cudaFuncSetAttribute(k_gemm2, cudaFuncAttributeMaxDynamicSharedMemorySize, G2_SMEM);
        attr_done = 1;
    }

    // launch order keeps k_gemm1 at ncu's capture slot (#4)
    k_init<<<1, 32>>>();
    k_router<<<(T_TOK * 32) / 256, 256>>>(x, gw);
    k_conv<<<(N4_X + 3 * N4_W + 255) / 256, 256>>>((const float4*)x, (const float4*)wg,
                                                   (const float4*)wu, (const float4*)wd);
    k_gemm1<<<dim3(T_TOK / 128, I_DIM / 64, N_EXP), 128, G1_SMEM>>>();
    k_gemm2<<<dim3(T_TOK / 128, H_DIM / 128, N_EXP), 128, G2_SMEM>>>();
    k_combine<<<(T_TOK * H_DIM + 255) / 256, 256>>>(out);
}

// round 8
// speedup vs baseline: 6.3819x; 1.0617x over previous
#include <cuda_runtime.h>
#include <cuda_fp16.h>
#include <math.h>
#include <stdint.h>

#define T_TOK 4096
#define H_DIM 2048
#define I_DIM 1024
#define N_EXP 8

// ---------------- scratch (static device globals; no allocation) ------------
__device__ int   g_count[N_EXP];
__device__ int   g_tok [N_EXP * T_TOK];
__device__ float g_wt  [N_EXP * T_TOK];
__device__ int   g_slot[N_EXP * T_TOK];
__device__ float g_part[(size_t)T_TOK * 2 * H_DIM];   // 64 MB

// converted fp16 operands
__device__ __half cx_hi [(size_t)T_TOK * H_DIM];
__device__ __half cwg_hi[(size_t)N_EXP * I_DIM * H_DIM];
__device__ __half cwu_hi[(size_t)N_EXP * I_DIM * H_DIM];
__device__ __half cwd_hi[(size_t)N_EXP * H_DIM * I_DIM];
__device__ __half act_hi[(size_t)N_EXP * T_TOK * I_DIM];

// ======================= helpers ============================================
__device__ __forceinline__ uint32_t smem_u32(const void* p) {
    uint32_t a;
    asm("{ .reg .u64 t; cvta.to.shared.u64 t, %1; cvt.u32.u64 %0, t; }"
        : "=r"(a) : "l"(p));
    return a;
}

__device__ __forceinline__ void cp16(uint32_t s, const void* g) {
    asm volatile("cp.async.cg.shared.global [%0], [%1], 16;"
                 :: "r"(s), "l"(g) : "memory");
}
#define CP_COMMIT() asm volatile("cp.async.commit_group;" ::: "memory")
#define CP_WAIT(n)  asm volatile("cp.async.wait_group %0;" :: "n"(n) : "memory")

__device__ __forceinline__ void ldm4(uint32_t& r0, uint32_t& r1,
                                     uint32_t& r2, uint32_t& r3, uint32_t a) {
    asm volatile("ldmatrix.sync.aligned.m8n8.x4.shared.b16 {%0,%1,%2,%3}, [%4];"
                 : "=r"(r0), "=r"(r1), "=r"(r2), "=r"(r3) : "r"(a));
}

__device__ __forceinline__ void mma16816(float* c, const uint32_t* a,
                                         uint32_t b0, uint32_t b1) {
    asm volatile(
        "mma.sync.aligned.m16n8k16.row.col.f32.f16.f16.f32 "
        "{%0,%1,%2,%3}, {%4,%5,%6,%7}, {%8,%9}, {%0,%1,%2,%3};"
        : "+f"(c[0]), "+f"(c[1]), "+f"(c[2]), "+f"(c[3])
        : "r"(a[0]), "r"(a[1]), "r"(a[2]), "r"(a[3]), "r"(b0), "r"(b1));
}

__device__ __forceinline__ uint32_t pack2h(float a, float b) {
    __half2 hv = __floats2half2_rn(a, b);
    return *reinterpret_cast<uint32_t*>(&hv);
}

// ---------------- init ------------------------------------------------------
__global__ void k_init() {
    if (threadIdx.x < N_EXP) g_count[threadIdx.x] = 0;
}

// ---------------- conversion (single launch) --------------------------------
#define N4_X (T_TOK * H_DIM / 4)
#define N4_W (N_EXP * I_DIM * H_DIM / 4)
__global__ void k_conv(const float4* __restrict__ x,  const float4* __restrict__ wg,
                       const float4* __restrict__ wu, const float4* __restrict__ wd) {
    int i = blockIdx.x * 256 + threadIdx.x;
    const float4* src;
    uint2* dst;
    int j = i;
    if (i < N4_X)                { src = x;  dst = (uint2*)cx_hi; }
    else if ((j -= N4_X) < N4_W) { src = wg; dst = (uint2*)cwg_hi; }
    else if ((j -= N4_W) < N4_W) { src = wu; dst = (uint2*)cwu_hi; }
    else if ((j -= N4_W) < N4_W) { src = wd; dst = (uint2*)cwd_hi; }
    else return;
    float4 v = src[j];
    dst[j] = make_uint2(pack2h(v.x, v.y), pack2h(v.z, v.w));
}

// ---------------- router ----------------------------------------------------
__global__ void k_router(const float* __restrict__ x,
                         const float* __restrict__ gw) {
    int gid  = blockIdx.x * blockDim.x + threadIdx.x;
    int t    = gid >> 5;
    int lane = gid & 31;
    if (t >= T_TOK) return;

    const float* xr = x + (size_t)t * H_DIM;
    float acc[N_EXP];
#pragma unroll
    for (int e = 0; e < N_EXP; e++) acc[e] = 0.f;

    for (int h = lane; h < H_DIM; h += 32) {
        float xv = xr[h];
#pragma unroll
        for (int e = 0; e < N_EXP; e++) acc[e] += xv * gw[e * H_DIM + h];
    }
#pragma unroll
    for (int e = 0; e < N_EXP; e++) {
#pragma unroll
        for (int o = 16; o > 0; o >>= 1)
            acc[e] += __shfl_xor_sync(0xffffffffu, acc[e], o);
    }

    if (lane == 0) {
        float m = acc[0];
#pragma unroll
        for (int e = 1; e < N_EXP; e++) m = fmaxf(m, acc[e]);
        float p[N_EXP];
        float s = 0.f;
#pragma unroll
        for (int e = 0; e < N_EXP; e++) { p[e] = expf(acc[e] - m); s += p[e]; }
        float inv = 1.f / s;
#pragma unroll
        for (int e = 0; e < N_EXP; e++) p[e] *= inv;

        int e0 = 0;
#pragma unroll
        for (int e = 1; e < N_EXP; e++) if (p[e] > p[e0]) e0 = e;
        int e1 = -1;
#pragma unroll
        for (int e = 0; e < N_EXP; e++) {
            if (e == e0) continue;
            if (e1 < 0 || p[e] > p[e1]) e1 = e;
        }
        float den = p[e0] + p[e1];
        float w0 = p[e0] / den;
        float w1 = p[e1] / den;

        int pos0 = atomicAdd(&g_count[e0], 1);
        g_tok [e0 * T_TOK + pos0] = t;
        g_wt  [e0 * T_TOK + pos0] = w0;
        g_slot[e0 * T_TOK + pos0] = 0;

        int pos1 = atomicAdd(&g_count[e1], 1);
        g_tok [e1 * T_TOK + pos1] = t;
        g_wt  [e1 * T_TOK + pos1] = w1;
        g_slot[e1 * T_TOK + pos1] = 1;
    }
}

// ======================= GEMM1: silu(x Wg^T) * (x Wu^T) =====================
// CTA: 128 threads (4 warps), tile 128 tokens x 64 inter (gate+up).
// Warp tile 64x64. kc=64, 2-stage cp.async. pitch 144B.
// stage (36864B): A(18432 = 128x144) Bg(9216 = 64x144) Bu(9216)
#define G1_PITCH 144
#define G1_STG   36864
#define G1_SMEM  (2 * G1_STG + 512)

__device__ __forceinline__ void g1_load(uint32_t sbase, int st, int kt,
                                        int e, int col0, const int* toks_s) {
    const int k0 = kt * 64;
    const uint32_t sb = sbase + st * G1_STG;
    const int tid = threadIdx.x;
#pragma unroll
    for (int j = 0; j < 8; j++) {             // A: 128 rows x 8 chunks of 16B
        int chunk = tid + j * 128;
        int row = chunk >> 3, c = chunk & 7;
        size_t go = (size_t)toks_s[row] * H_DIM + k0 + c * 8;
        cp16(sb + row * G1_PITCH + c * 16, cx_hi + go);
    }
#pragma unroll
    for (int j = 0; j < 4; j++) {             // Bg/Bu: 64 rows x 8 chunks each
        int chunk = tid + j * 128;
        int row = chunk >> 3, c = chunk & 7;
        size_t go = ((size_t)(e * I_DIM + col0 + row)) * H_DIM + k0 + c * 8;
        cp16(sb + 18432 + row * G1_PITCH + c * 16, cwg_hi + go);
        cp16(sb + 27648 + row * G1_PITCH + c * 16, cwu_hi + go);
    }
}

__global__ __launch_bounds__(128, 2) void k_gemm1() {
    extern __shared__ char smem[];
    const int e    = blockIdx.z;
    const int n    = g_count[e];
    const int row0 = blockIdx.x * 128;
    if (row0 >= n) return;
    const int col0 = blockIdx.y * 64;
    const int tid  = threadIdx.x;
    const int l    = tid & 31;
    const int w    = tid >> 5;
    const int m0   = (w & 1) * 64;
    const bool isU = (w >> 1);                // warps 2,3 = up

    int* toks_s = (int*)(smem + 2 * G1_STG);
    if (tid < 128) {
        int r = row0 + tid;
        toks_s[tid] = (r < n) ? g_tok[e * T_TOK + r] : 0;
    }
    __syncthreads();

    const uint32_t sbase = smem_u32(smem);

    float acc[4][8][4];
#pragma unroll
    for (int a = 0; a < 4; a++)
#pragma unroll
        for (int b = 0; b < 8; b++)
#pragma unroll
            for (int c = 0; c < 4; c++) acc[a][b][c] = 0.f;

    const int KT = H_DIM / 64;  // 32
    g1_load(sbase, 0, 0, e, col0, toks_s);
    CP_COMMIT();

    const uint32_t arow = (uint32_t)((l & 7) + ((l >> 3) & 1) * 8);
    const uint32_t brow = (uint32_t)((l & 7) + ((l >> 4) & 1) * 8);

    for (int kt = 0; kt < KT; kt++) {
        if (kt + 1 < KT) { g1_load(sbase, (kt + 1) & 1, kt + 1, e, col0, toks_s); CP_COMMIT(); }
        if (kt + 1 < KT) CP_WAIT(1); else CP_WAIT(0);
        __syncthreads();

        const uint32_t sA = sbase + (kt & 1) * G1_STG;
        const uint32_t sB = sA + (isU ? 27648 : 18432);

#pragma unroll
        for (int ks = 0; ks < 4; ks++) {
            const uint32_t acol = (uint32_t)(((l >> 4) * 8 + ks * 16) * 2);
            const uint32_t bcol = (uint32_t)((((l >> 3) & 1) * 8 + ks * 16) * 2);
            uint32_t ah[4][4];
#pragma unroll
            for (int mt = 0; mt < 4; mt++)
                ldm4(ah[mt][0], ah[mt][1], ah[mt][2], ah[mt][3],
                     sA + (m0 + mt * 16 + arow) * G1_PITCH + acol);
#pragma unroll
            for (int np = 0; np < 4; np++) {
                uint32_t bh[4];
                ldm4(bh[0], bh[1], bh[2], bh[3],
                     sB + (np * 16 + brow) * G1_PITCH + bcol);
#pragma unroll
                for (int mt = 0; mt < 4; mt++) {
                    mma16816(acc[mt][np * 2 + 0], ah[mt], bh[0], bh[1]);
                    mma16816(acc[mt][np * 2 + 1], ah[mt], bh[2], bh[3]);
                }
            }
        }
        __syncthreads();
    }

    // epilogue: up warps (2,3) -> smem, gate warps (0,1) compute silu(g)*u
    float* Ub = (float*)smem;   // 128 x 72 floats = 36864B = stage 0
    if (isU) {
#pragma unroll
        for (int mt = 0; mt < 4; mt++)
#pragma unroll
            for (int nt = 0; nt < 8; nt++) {
                int m  = m0 + mt * 16 + (l >> 2);
                int cc = nt * 8 + (l & 3) * 2;
                *(float2*)&Ub[m * 72 + cc]       = make_float2(acc[mt][nt][0], acc[mt][nt][1]);
                *(float2*)&Ub[(m + 8) * 72 + cc] = make_float2(acc[mt][nt][2], acc[mt][nt][3]);
            }
    }
    __syncthreads();
    if (!isU) {
#pragma unroll
        for (int mt = 0; mt < 4; mt++)
#pragma unroll
            for (int nt = 0; nt < 8; nt++) {
                int m  = m0 + mt * 16 + (l >> 2);
                int cc = nt * 8 + (l & 3) * 2;
#pragma unroll
                for (int half = 0; half < 2; half++) {
                    int mm = m + half * 8;
                    int rr = row0 + mm;
                    if (rr < n) {
                        float2 u = *(float2*)&Ub[mm * 72 + cc];
                        float g0 = acc[mt][nt][half * 2 + 0];
                        float g1 = acc[mt][nt][half * 2 + 1];
                        float a0 = g0 / (1.f + __expf(-g0)) * u.x;
                        float a1 = g1 / (1.f + __expf(-g1)) * u.y;
                        size_t idx = ((size_t)e * T_TOK + rr) * I_DIM + col0 + cc;
                        *(uint32_t*)(act_hi + idx) = pack2h(a0, a1);
                    }
                }
            }
    }
}

// ======================= GEMM2: part = rw * (act Wd^T) ======================
// CTA: 128 threads (4 warps, 2x2), tile 128 rows x 128 H-cols. Warp 64x64.
// kc=64, 2-stage. stage (36864B): A(18432) B(18432)
#define G2_PITCH 144
#define G2_STG   36864
#define G2_SMEM  (2 * G2_STG + 2048)

__device__ __forceinline__ void g2_load(uint32_t sbase, int st, int kt,
                                        int e, int row0, int col0) {
    const int k0 = kt * 64;
    const uint32_t sb = sbase + st * G2_STG;
    const int tid = threadIdx.x;
#pragma unroll
    for (int j = 0; j < 8; j++) {
        int chunk = tid + j * 128;
        int row = chunk >> 3, c = chunk & 7;
        size_t ga = ((size_t)e * T_TOK + row0 + row) * I_DIM + k0 + c * 8;
        cp16(sb + row * G2_PITCH + c * 16, act_hi + ga);
        size_t gb = ((size_t)(e * H_DIM + col0 + row)) * I_DIM + k0 + c * 8;
        cp16(sb + 18432 + row * G2_PITCH + c * 16, cwd_hi + gb);
    }
}

__global__ __launch_bounds__(128, 2) void k_gemm2() {
    extern __shared__ char smem[];
    const int e    = blockIdx.z;
    const int n    = g_count[e];
    const int row0 = blockIdx.x * 128;
    if (row0 >= n) return;
    const int col0 = blockIdx.y * 128;
    const int tid  = threadIdx.x;
    const int l    = tid & 31;
    const int w    = tid >> 5;
    const int m0   = (w & 1) * 64;
    const int nw0  = (w >> 1) * 64;

    int*   toks_s = (int*)  (smem + 2 * G2_STG);
    float* ws_s   = (float*)(smem + 2 * G2_STG + 512);
    int*   ks_s   = (int*)  (smem + 2 * G2_STG + 1024);
    if (tid < 128) {
        int r = row0 + tid;
        if (r < n) {
            toks_s[tid] = g_tok [e * T_TOK + r];
            ws_s[tid]   = g_wt  [e * T_TOK + r];
            ks_s[tid]   = g_slot[e * T_TOK + r];
        } else { toks_s[tid] = 0; ws_s[tid] = 0.f; ks_s[tid] = 0; }
    }
    __syncthreads();

    const uint32_t sbase = smem_u32(smem);

    float acc[4][8][4];
#pragma unroll
    for (int a = 0; a < 4; a++)
#pragma unroll
        for (int b = 0; b < 8; b++)
#pragma unroll
            for (int c = 0; c < 4; c++) acc[a][b][c] = 0.f;

    const int KT = I_DIM / 64;  // 16
    g2_load(sbase, 0, 0, e, row0, col0);
    CP_COMMIT();

    const uint32_t arow = (uint32_t)((l & 7) + ((l >> 3) & 1) * 8);
    const uint32_t brow = (uint32_t)((l & 7) + ((l >> 4) & 1) * 8);

    for (int kt = 0; kt < KT; kt++) {
        if (kt + 1 < KT) { g2_load(sbase, (kt + 1) & 1, kt + 1, e, row0, col0); CP_COMMIT(); }
        if (kt + 1 < KT) CP_WAIT(1); else CP_WAIT(0);
        __syncthreads();

        const uint32_t sA = sbase + (kt & 1) * G2_STG;
        const uint32_t sB = sA + 18432;

#pragma unroll
        for (int ks = 0; ks < 4; ks++) {
            const uint32_t acol = (uint32_t)(((l >> 4) * 8 + ks * 16) * 2);
            const uint32_t bcol = (uint32_t)((((l >> 3) & 1) * 8 + ks * 16) * 2);
            uint32_t ah[4][4];
#pragma unroll
            for (int mt = 0; mt < 4; mt++)
                ldm4(ah[mt][0], ah[mt][1], ah[mt][2], ah[mt][3],
                     sA + (m0 + mt * 16 + arow) * G2_PITCH + acol);
#pragma unroll
            for (int np = 0; np < 4; np++) {
                uint32_t bh[4];
                ldm4(bh[0], bh[1], bh[2], bh[3],
                     sB + (nw0 + np * 16 + brow) * G2_PITCH + bcol);
#pragma unroll
                for (int mt = 0; mt < 4; mt++) {
                    mma16816(acc[mt][np * 2 + 0], ah[mt], bh[0], bh[1]);
                    mma16816(acc[mt][np * 2 + 1], ah[mt], bh[2], bh[3]);
                }
            }
        }
        __syncthreads();
    }

    // epilogue: scale by routing weight, plain float2 stores into g_part
#pragma unroll
    for (int mt = 0; mt < 4; mt++)
#pragma unroll
        for (int nt = 0; nt < 8; nt++) {
            int m  = m0 + mt * 16 + (l >> 2);
            int cc = nw0 + nt * 8 + (l & 3) * 2;
#pragma unroll
            for (int half = 0; half < 2; half++) {
                int mm = m + half * 8;
                if (row0 + mm < n) {
                    int   t  = toks_s[mm];
                    int   k  = ks_s[mm];
                    float wt = ws_s[mm];
                    float2 v = make_float2(acc[mt][nt][half * 2 + 0] * wt,
                                           acc[mt][nt][half * 2 + 1] * wt);
                    *(float2*)&g_part[((size_t)t * 2 + k) * H_DIM + col0 + cc] = v;
                }
            }
        }
}

// ---------------- combine ----------------------------------------------------
__global__ void k_combine(float* __restrict__ out) {
    int i = blockIdx.x * 256 + threadIdx.x;
    if (i >= T_TOK * H_DIM) return;
    int t = i >> 11;
    int h = i & (H_DIM - 1);
    out[i] = g_part[((size_t)t * 2 + 0) * H_DIM + h] +
             g_part[((size_t)t * 2 + 1) * H_DIM + h];
}

// ---------------- launch -----------------------------------------------------
extern "C" void kernel_launch(void* const* d_in, const int* in_sizes, int n_in,
                              void* d_out, int out_size) {
    const float* x  = (const float*)d_in[0];
    const float* gw = (const float*)d_in[1];
    const float* wg = (const float*)d_in[2];
    const float* wu = (const float*)d_in[3];
    const float* wd = (const float*)d_in[4];
    float* out = (float*)d_out;

    static int attr_done = 0;
    if (!attr_done) {
        cudaFuncSetAttribute(k_gemm1, cudaFuncAttributeMaxDynamicSharedMemorySize, G1_SMEM);
        cudaFuncSetAttribute(k_gemm2, cudaFuncAttributeMaxDynamicSharedMemorySize, G2_SMEM);
        attr_done = 1;
    }

    // launch order keeps k_gemm1 at ncu's capture slot (#4)
    k_init<<<1, 32>>>();
    k_router<<<(T_TOK * 32) / 256, 256>>>(x, gw);
    k_conv<<<(N4_X + 3 * N4_W + 255) / 256, 256>>>((const float4*)x, (const float4*)wg,
                                                   (const float4*)wu, (const float4*)wd);
    k_gemm1<<<dim3(T_TOK / 128, I_DIM / 64, N_EXP), 128, G1_SMEM>>>();
    k_gemm2<<<dim3(T_TOK / 128, H_DIM / 128, N_EXP), 128, G2_SMEM>>>();
    k_combine<<<(T_TOK * H_DIM + 255) / 256, 256>>>(out);
}